// round 11
// baseline (speedup 1.0000x reference)
#include <cuda_runtime.h>
#include <cuda_bf16.h>
#include <cuda_pipeline.h>
#include <math.h>
#include <stdint.h>

// ---------------------------------------------------------------------------
// Mamba block forward.
// G1/G4: int8x3 split-precision IMMA m16n8k32, warp tile 32x64 (8 warps).
// G2/G3: bf16x3 mma.sync m16n8k16; G2 retiled BM=32 for full-chip occupancy.
// Scan: 2 states per thread (float2 B/C), 3-shfl reduce, prefetch pipeline.
// Conservative build: static smem <=48KB, __pipeline intrinsics only.
// ---------------------------------------------------------------------------

#define D_MODEL  1024
#define D_STATE  16
#define D_CONV   4
#define D_INNER  2048
#define DT_RANK  64
#define BATCH    2
#define SEQ      2048
#define M_TOK    (BATCH * SEQ)   // 4096

typedef __nv_bfloat16 bf16;

// fp32 scratch
__device__ float g_xz  [(size_t)M_TOK * 2 * D_INNER];
__device__ float g_xc  [(size_t)M_TOK * D_INNER];
__device__ float g_xdbl[(size_t)M_TOK * 96];
__device__ float g_dt  [(size_t)M_TOK * D_INNER];
__device__ float g_y   [(size_t)M_TOK * D_INNER];

// int8 operands (+ per-row scales) for G1/G4
__device__ char  q_xa [(size_t)M_TOK * D_MODEL],  q_xb [(size_t)M_TOK * D_MODEL];
__device__ char  q_w1a[(size_t)2*D_INNER*D_MODEL],q_w1b[(size_t)2*D_INNER*D_MODEL];
__device__ char  q_oa [(size_t)D_MODEL * D_INNER],q_ob [(size_t)D_MODEL * D_INNER];
__device__ char  q_ya [(size_t)M_TOK * D_INNER],  q_yb [(size_t)M_TOK * D_INNER];
__device__ float g_s_x[M_TOK], g_s_w1[2*D_INNER], g_s_o[D_MODEL], g_s_y[M_TOK];

// bf16 hi/lo operands for G2/G3
__device__ bf16 g_xch[(size_t)M_TOK * D_INNER],  g_xcl[(size_t)M_TOK * D_INNER];
__device__ bf16 g_xwh[(size_t)96 * D_INNER],     g_xwl[(size_t)96 * D_INNER];
__device__ bf16 g_dth[(size_t)M_TOK * DT_RANK],  g_dtl[(size_t)M_TOK * DT_RANK];
__device__ bf16 g_dwh[(size_t)D_INNER * DT_RANK],g_dwl[(size_t)D_INNER * DT_RANK];

// ---------------------------------------------------------------------------
__device__ __forceinline__ uint32_t smem_u32(const void* p) {
    uint32_t a;
    asm("{ .reg .u64 t; cvta.to.shared.u64 t, %1; cvt.u32.u64 %0, t; }"
        : "=r"(a) : "l"(p));
    return a;
}

#define LDSM4(r0, r1, r2, r3, addr) \
    asm volatile("ldmatrix.sync.aligned.m8n8.x4.shared.b16 {%0,%1,%2,%3}, [%4];" \
        : "=r"(r0), "=r"(r1), "=r"(r2), "=r"(r3) : "r"(addr))

#define MMA_BF16(d, a, b) \
    asm volatile("mma.sync.aligned.m16n8k16.row.col.f32.bf16.bf16.f32 " \
        "{%0,%1,%2,%3}, {%4,%5,%6,%7}, {%8,%9}, {%0,%1,%2,%3};" \
        : "+f"((d)[0]), "+f"((d)[1]), "+f"((d)[2]), "+f"((d)[3]) \
        : "r"((a)[0]), "r"((a)[1]), "r"((a)[2]), "r"((a)[3]), \
          "r"((b)[0]), "r"((b)[1]))

#define MMA_S8(d, a, b) \
    asm volatile("mma.sync.aligned.m16n8k32.row.col.s32.s8.s8.s32 " \
        "{%0,%1,%2,%3}, {%4,%5,%6,%7}, {%8,%9}, {%0,%1,%2,%3};" \
        : "+r"((d)[0]), "+r"((d)[1]), "+r"((d)[2]), "+r"((d)[3]) \
        : "r"((a)[0]), "r"((a)[1]), "r"((a)[2]), "r"((a)[3]), \
          "r"((b)[0]), "r"((b)[1]))

// ---------------------------------------------------------------------------
// int8 GEMM (G1/G4):  C[m,n] = sA[m]*sB[n]*(Q1a.Q1b + (Q2a.Q1b + Q1a.Q2b)/128)
// K-tile = 32 int8 (32B rows, 2x16B chunks, XOR swizzle (r>>2)&1).
// 3-stage cp.async pipeline, 1 sync/iter.
// ---------------------------------------------------------------------------
template<int BM, int BN, int WM, int WN, int THREADS>
__device__ __forceinline__ void stage_load_i8(
    char* sb, const char* a1, const char* a2, int lda,
    const char* b1, const char* b2, int ldb, int koff, int tid)
{
    constexpr int RT = 2 * BM + 2 * BN;
#pragma unroll
    for (int e = tid; e < RT * 2; e += THREADS) {
        const int r = e >> 1, c = e & 1;
        char* dst = sb + (r << 5) + ((c ^ ((r >> 2) & 1)) << 4);
        const char* src;
        if (r < BM)               src = a1 + (long)r * lda + koff + c * 16;
        else if (r < 2 * BM)      src = a2 + (long)(r - BM) * lda + koff + c * 16;
        else if (r < 2 * BM + BN) src = b1 + (long)(r - 2 * BM) * ldb + koff + c * 16;
        else                      src = b2 + (long)(r - 2 * BM - BN) * ldb + koff + c * 16;
        __pipeline_memcpy_async(dst, src, 16);
    }
    __pipeline_commit();
}

template<int BM, int BN, int WM, int WN, int THREADS>
__global__ void __launch_bounds__(THREADS)
gemm_imma(const char* __restrict__ A1, const char* __restrict__ A2, int lda,
          const char* __restrict__ B1, const char* __restrict__ B2, int ldb,
          const float* __restrict__ sA, const float* __restrict__ sB,
          float* __restrict__ C, int ldc, int K)
{
    constexpr int STAGE_B = (2 * BM + 2 * BN) * 32;   // bytes per stage
    constexpr int WARPS_N = BN / WN;
    constexpr int MA = WM / 16;
    constexpr int NA = WN / 8;                        // even

    __shared__ __align__(128) char smem[3 * STAGE_B];

    const int tid = threadIdx.x, wid = tid >> 5, lane = tid & 31;
    const int wm = wid / WARPS_N, wn = wid % WARPS_N;
    const int m0 = blockIdx.y * BM;
    const int n0 = blockIdx.x * BN;
    const int KT = K >> 5;

    const char* a1 = A1 + (long)m0 * lda;
    const char* a2 = A2 + (long)m0 * lda;
    const char* b1 = B1 + (long)n0 * ldb;
    const char* b2 = B2 + (long)n0 * ldb;

    int acc1[MA][NA][4], acc2[MA][NA][4];
#pragma unroll
    for (int i = 0; i < MA; i++)
#pragma unroll
        for (int j = 0; j < NA; j++)
#pragma unroll
            for (int e = 0; e < 4; e++) { acc1[i][j][e] = 0; acc2[i][j][e] = 0; }

    const int a_row  = wm * WM + (lane & 15);
    const int a_csel = lane >> 4;
    const int bg     = lane >> 3;
    const int b_row  = wn * WN + (lane & 7) + ((bg >> 1) << 3);
    const int b_csel = bg & 1;

    const uint32_t s0 = smem_u32(smem);

    stage_load_i8<BM,BN,WM,WN,THREADS>(smem, a1, a2, lda, b1, b2, ldb, 0, tid);
    if (KT > 1)
        stage_load_i8<BM,BN,WM,WN,THREADS>(smem + STAGE_B, a1, a2, lda, b1, b2, ldb, 32, tid);
    else
        __pipeline_commit();

    int cs = 0;
    for (int kt = 0; kt < KT; ++kt) {
        __pipeline_wait_prior(1);
        __syncthreads();

        const uint32_t base = s0 + cs * STAGE_B;
        const uint32_t pA1 = base;
        const uint32_t pA2 = base + BM * 32;
        const uint32_t pB1 = base + 2 * BM * 32;
        const uint32_t pB2 = pB1 + BN * 32;

        uint32_t ar1[MA][4], ar2[MA][4], br1[NA][2], br2[NA][2];
#pragma unroll
        for (int ma = 0; ma < MA; ++ma) {
            const int r = a_row + ma * 16;
            const uint32_t off = r * 32 + ((a_csel ^ ((r >> 2) & 1)) << 4);
            LDSM4(ar1[ma][0], ar1[ma][1], ar1[ma][2], ar1[ma][3], pA1 + off);
            LDSM4(ar2[ma][0], ar2[ma][1], ar2[ma][2], ar2[ma][3], pA2 + off);
        }
#pragma unroll
        for (int p = 0; p < NA / 2; ++p) {
            const int r = b_row + p * 16;
            const uint32_t off = r * 32 + ((b_csel ^ ((r >> 2) & 1)) << 4);
            LDSM4(br1[2*p][0], br1[2*p][1], br1[2*p+1][0], br1[2*p+1][1], pB1 + off);
            LDSM4(br2[2*p][0], br2[2*p][1], br2[2*p+1][0], br2[2*p+1][1], pB2 + off);
        }
#pragma unroll
        for (int ma = 0; ma < MA; ++ma)
#pragma unroll
            for (int na = 0; na < NA; ++na) {
                MMA_S8(acc1[ma][na], ar1[ma], br1[na]);
                MMA_S8(acc2[ma][na], ar2[ma], br1[na]);
                MMA_S8(acc2[ma][na], ar1[ma], br2[na]);
            }

        if (kt + 2 < KT) {
            int ls = cs + 2; if (ls >= 3) ls -= 3;
            stage_load_i8<BM,BN,WM,WN,THREADS>(smem + ls * STAGE_B,
                a1, a2, lda, b1, b2, ldb, (kt + 2) * 32, tid);
        } else {
            __pipeline_commit();
        }
        if (++cs == 3) cs = 0;
    }

    // epilogue: C = sA*sB*(acc1 + acc2/128)
    const int er = lane >> 2, ec = (lane & 3) * 2;
#pragma unroll
    for (int ma = 0; ma < MA; ++ma) {
        const int m = m0 + wm * WM + ma * 16 + er;
        const float sa0 = sA[m], sa1 = sA[m + 8];
#pragma unroll
        for (int na = 0; na < NA; ++na) {
            const int n = n0 + wn * WN + na * 8 + ec;
            const float sb0 = sB[n], sb1 = sB[n + 1];
            float2 v0, v1;
            v0.x = sa0 * sb0 * ((float)acc1[ma][na][0] + (float)acc2[ma][na][0] * 0.0078125f);
            v0.y = sa0 * sb1 * ((float)acc1[ma][na][1] + (float)acc2[ma][na][1] * 0.0078125f);
            v1.x = sa1 * sb0 * ((float)acc1[ma][na][2] + (float)acc2[ma][na][2] * 0.0078125f);
            v1.y = sa1 * sb1 * ((float)acc1[ma][na][3] + (float)acc2[ma][na][3] * 0.0078125f);
            *(float2*)(C + (long)m * ldc + n)       = v0;
            *(float2*)(C + (long)(m + 8) * ldc + n) = v1;
        }
    }
}

// ---------------------------------------------------------------------------
// bf16x3 GEMM (G2/G3) — proven path (BK=16, 3-stage).
// ---------------------------------------------------------------------------
template<int BM, int BN, int THREADS>
__device__ __forceinline__ void stage_load(
    bf16* sb, const bf16* aH, const bf16* aL, int lda,
    const bf16* bH, const bf16* bL, int ldb, int koff, int tid)
{
    constexpr int RT  = 2 * BM + 2 * BN;
#pragma unroll
    for (int e = tid; e < RT * 2; e += THREADS) {
        const int r = e >> 1, c = e & 1;
        bf16* dst = sb + (r << 4) + ((c ^ ((r >> 2) & 1)) << 3);
        const bf16* src;
        if (r < BM)               src = aH + (long)r * lda + koff + c * 8;
        else if (r < 2 * BM)      src = aL + (long)(r - BM) * lda + koff + c * 8;
        else if (r < 2 * BM + BN) src = bH + (long)(r - 2 * BM) * ldb + koff + c * 8;
        else                      src = bL + (long)(r - 2 * BM - BN) * ldb + koff + c * 8;
        __pipeline_memcpy_async(dst, src, 16);
    }
    __pipeline_commit();
}

template<int BM, int BN, int WM, int WN, int THREADS, int EPI>
__global__ void __launch_bounds__(THREADS)
gemm_mma(const bf16* __restrict__ Ah, const bf16* __restrict__ Al, int lda,
         const bf16* __restrict__ Bh, const bf16* __restrict__ Bl, int ldb,
         float* __restrict__ C, int ldc, int K,
         const float* __restrict__ bias)
{
    constexpr int STAGE_E = (2 * BM + 2 * BN) * 16;
    constexpr int WARPS_N = BN / WN;
    constexpr int MA = WM / 16;
    constexpr int NA = WN / 8;

    __shared__ bf16 smem[3 * STAGE_E];

    const int tid = threadIdx.x, wid = tid >> 5, lane = tid & 31;
    const int wm = wid / WARPS_N, wn = wid % WARPS_N;
    const int m0 = blockIdx.y * BM;
    const int n0 = blockIdx.x * BN;
    const int KT = K >> 4;

    const bf16* aH = Ah + (long)m0 * lda;
    const bf16* aL = Al + (long)m0 * lda;
    const bf16* bH = Bh + (long)n0 * ldb;
    const bf16* bL = Bl + (long)n0 * ldb;

    float acc[MA][NA][4];
#pragma unroll
    for (int i = 0; i < MA; i++)
#pragma unroll
        for (int j = 0; j < NA; j++)
#pragma unroll
            for (int e = 0; e < 4; e++) acc[i][j][e] = 0.f;

    const int a_row  = wm * WM + (lane & 15);
    const int a_csel = lane >> 4;
    const int bg     = lane >> 3;
    const int b_row  = wn * WN + (lane & 7) + ((bg >> 1) << 3);
    const int b_csel = bg & 1;

    const uint32_t s0 = smem_u32(smem);

    stage_load<BM, BN, THREADS>(smem, aH, aL, lda, bH, bL, ldb, 0, tid);
    if (KT > 1)
        stage_load<BM, BN, THREADS>(smem + STAGE_E, aH, aL, lda, bH, bL, ldb, 16, tid);
    else
        __pipeline_commit();

    int cs = 0;
    for (int kt = 0; kt < KT; ++kt) {
        __pipeline_wait_prior(1);
        __syncthreads();

        const uint32_t base = s0 + cs * (STAGE_E * 2);
        const uint32_t pAh = base;
        const uint32_t pAl = base + BM * 32;
        const uint32_t pBh = base + 2 * BM * 32;
        const uint32_t pBl = pBh + BN * 32;

        uint32_t ar[MA][4], alr[MA][4], br[NA][2], blr[NA][2];
#pragma unroll
        for (int ma = 0; ma < MA; ++ma) {
            const int r = a_row + ma * 16;
            const uint32_t off = r * 32 + ((a_csel ^ ((r >> 2) & 1)) << 4);
            LDSM4(ar[ma][0],  ar[ma][1],  ar[ma][2],  ar[ma][3],  pAh + off);
            LDSM4(alr[ma][0], alr[ma][1], alr[ma][2], alr[ma][3], pAl + off);
        }
#pragma unroll
        for (int p = 0; p < NA / 2; ++p) {
            const int r = b_row + p * 16;
            const uint32_t off = r * 32 + ((b_csel ^ ((r >> 2) & 1)) << 4);
            LDSM4(br[2*p][0],  br[2*p][1],  br[2*p+1][0],  br[2*p+1][1],  pBh + off);
            LDSM4(blr[2*p][0], blr[2*p][1], blr[2*p+1][0], blr[2*p+1][1], pBl + off);
        }
#pragma unroll
        for (int ma = 0; ma < MA; ++ma)
#pragma unroll
            for (int na = 0; na < NA; ++na) {
                MMA_BF16(acc[ma][na], ar[ma],  br[na]);
                MMA_BF16(acc[ma][na], alr[ma], br[na]);
                MMA_BF16(acc[ma][na], ar[ma],  blr[na]);
            }

        if (kt + 2 < KT) {
            int ls = cs + 2; if (ls >= 3) ls -= 3;
            stage_load<BM, BN, THREADS>(smem + ls * STAGE_E,
                                        aH, aL, lda, bH, bL, ldb, (kt + 2) * 16, tid);
        } else {
            __pipeline_commit();
        }
        if (++cs == 3) cs = 0;
    }

    const int er = lane >> 2, ec = (lane & 3) * 2;
#pragma unroll
    for (int ma = 0; ma < MA; ++ma) {
#pragma unroll
        for (int na = 0; na < NA; ++na) {
            const int m = m0 + wm * WM + ma * 16 + er;
            const int n = n0 + wn * WN + na * 8 + ec;
            float2 v0 = {acc[ma][na][0], acc[ma][na][1]};
            float2 v1 = {acc[ma][na][2], acc[ma][na][3]};
            if (EPI == 1) {
                const float b0 = bias[n], b1 = bias[n + 1];
                v0.x += b0; v0.y += b1; v1.x += b0; v1.y += b1;
                v0.x = (v0.x > 20.f) ? v0.x : log1pf(__expf(v0.x));
                v0.y = (v0.y > 20.f) ? v0.y : log1pf(__expf(v0.y));
                v1.x = (v1.x > 20.f) ? v1.x : log1pf(__expf(v1.x));
                v1.y = (v1.y > 20.f) ? v1.y : log1pf(__expf(v1.y));
            }
            *(float2*)(C + (long)m * ldc + n)       = v0;
            *(float2*)(C + (long)(m + 8) * ldc + n) = v1;
        }
    }
}

// ---------------------------------------------------------------------------
// Per-row int8x2 quantization: s = rowmax/127, q1 = rn(v/s), q2 = rn((v/s-q1)*128)
// ---------------------------------------------------------------------------
__global__ void __launch_bounds__(256)
quant_rows(const float* __restrict__ src, int cols,
           char* __restrict__ q1, char* __restrict__ q2,
           float* __restrict__ scale)
{
    __shared__ float red[8];
    const int row = blockIdx.x, tid = threadIdx.x;
    const float* rp = src + (long)row * cols;
    const int nv = cols >> 10;          // float4 groups per thread
    float4 v[2];
    float m = 0.f;
    for (int i = 0; i < nv; i++) {
        v[i] = *(const float4*)(rp + tid * 4 + i * 1024);
        m = fmaxf(m, fmaxf(fmaxf(fabsf(v[i].x), fabsf(v[i].y)),
                           fmaxf(fabsf(v[i].z), fabsf(v[i].w))));
    }
    for (int o = 16; o; o >>= 1) m = fmaxf(m, __shfl_xor_sync(0xffffffffu, m, o));
    if ((tid & 31) == 0) red[tid >> 5] = m;
    __syncthreads();
    if (tid < 32) {
        float t = (tid < 8) ? red[tid] : 0.f;
        for (int o = 4; o; o >>= 1) t = fmaxf(t, __shfl_xor_sync(0xffffffffu, t, o));
        if (tid == 0) red[0] = t;
    }
    __syncthreads();
    const float bm  = red[0];
    const float s   = (bm > 1e-30f) ? bm * (1.f / 127.f) : 1.f;
    const float rcp = (bm > 1e-30f) ? 127.f / bm : 0.f;
    for (int i = 0; i < nv; i++) {
        const long o = (long)row * cols + tid * 4 + i * 1024;
        float f[4] = {v[i].x, v[i].y, v[i].z, v[i].w};
        char c1[4], c2[4];
#pragma unroll
        for (int j = 0; j < 4; j++) {
            float t = f[j] * rcp;
            int a = __float2int_rn(t);
            int b = __float2int_rn((t - (float)a) * 128.f);
            c1[j] = (char)a; c2[j] = (char)b;
        }
        *(char4*)(q1 + o) = make_char4(c1[0], c1[1], c1[2], c1[3]);
        *(char4*)(q2 + o) = make_char4(c2[0], c2[1], c2[2], c2[3]);
    }
    if (tid == 0) scale[row] = s;
}

// ---------------------------------------------------------------------------
// fp32 -> bf16 hi/lo split (cols power of two; src row stride ld)
// ---------------------------------------------------------------------------
__global__ void cvt_split(const float* __restrict__ src, int ld, int lc,
                          bf16* __restrict__ hi, bf16* __restrict__ lo, long total)
{
    long i = (long)blockIdx.x * blockDim.x + threadIdx.x;
    if (i >= total) return;
    long r = i >> lc;
    int c = (int)(i & ((1 << lc) - 1));
    float v = src[r * ld + c];
    bf16 h = __float2bfloat16(v);
    hi[i] = h;
    lo[i] = __float2bfloat16(v - __bfloat162float(h));
}

// ---------------------------------------------------------------------------
// Depthwise causal conv (4-tap) + SiLU + bf16 hi/lo emit (feeds G2)
// ---------------------------------------------------------------------------
__global__ void conv_silu_kernel(const float* __restrict__ conv_w,
                                 const float* __restrict__ conv_b)
{
    long idx = (long)blockIdx.x * blockDim.x + threadIdx.x;
    if (idx >= (long)M_TOK * D_INNER) return;
    int d = (int)(idx & (D_INNER - 1));
    long m = idx >> 11;
    int t = (int)(m & (SEQ - 1));
    long row0 = m - t;

    float acc = conv_b[d];
    const float* w = conv_w + d * 4;
#pragma unroll
    for (int j = 0; j < D_CONV; j++) {
        int tt = t - (D_CONV - 1) + j;
        if (tt >= 0)
            acc = fmaf(g_xz[(row0 + tt) * (2 * D_INNER) + d], w[j], acc);
    }
    float s = __fdividef(1.f, 1.f + __expf(-acc));
    float v = acc * s;
    long o = m * D_INNER + d;
    g_xc[o] = v;
    bf16 h = __float2bfloat16(v);
    g_xch[o] = h;
    g_xcl[o] = __float2bfloat16(v - __bfloat162float(h));
}

// ---------------------------------------------------------------------------
// Selective scan v2: one thread per (batch, channel, state-pair).
// Thread owns states 2*sp and 2*sp+1 -> float2 B/C loads, two independent
// h-chains, 3-shfl 8-lane reduce. Software-pipelined loads.
// ---------------------------------------------------------------------------
__global__ void __launch_bounds__(128)
scan_kernel(const float* __restrict__ A_log, const float* __restrict__ Dp)
{
    int tid = blockIdx.x * 128 + threadIdx.x;
    int sp = tid & 7;            // state pair index: states 2sp, 2sp+1
    int c  = tid >> 3;           // channel 0..4095
    int d  = c & (D_INNER - 1);
    int b  = c >> 11;
    int s0i = sp * 2;

    const float a0 = -__expf(A_log[d * D_STATE + s0i]);
    const float a1 = -__expf(A_log[d * D_STATE + s0i + 1]);
    const float Dv = Dp[d];
    float h0 = 0.f, h1 = 0.f;

    const float* dt_p = g_dt   + (long)b * SEQ * D_INNER + d;
    const float* xc_p = g_xc   + (long)b * SEQ * D_INNER + d;
    const float* z_p  = g_xz   + (long)b * SEQ * (2 * D_INNER) + D_INNER + d;
    const float* bc_p = g_xdbl + (long)b * SEQ * 96 + DT_RANK + s0i;
    long yo = (long)b * SEQ * D_INNER + d;

    // prefetch t = 0
    float dtc = __ldg(dt_p), xvc = __ldg(xc_p);
    float2 Bvc = *(const float2*)bc_p;
    float2 Cvc = *(const float2*)(bc_p + D_STATE);
    float zvc = (sp == 0) ? __ldg(z_p) : 0.f;

    for (int t = 0; t < SEQ; t++) {
        dt_p += D_INNER; xc_p += D_INNER; z_p += 2 * D_INNER; bc_p += 96;

        float dtn = 0.f, xvn = 0.f, zvn = 0.f;
        float2 Bvn = {0.f, 0.f}, Cvn = {0.f, 0.f};
        if (t + 1 < SEQ) {
            dtn = __ldg(dt_p); xvn = __ldg(xc_p);
            Bvn = *(const float2*)bc_p;
            Cvn = *(const float2*)(bc_p + D_STATE);
            if (sp == 0) zvn = __ldg(z_p);
        }

        float dA0 = __expf(dtc * a0);
        float dA1 = __expf(dtc * a1);
        float dtx = dtc * xvc;
        h0 = fmaf(dA0, h0, dtx * Bvc.x);
        h1 = fmaf(dA1, h1, dtx * Bvc.y);

        float p = fmaf(h1, Cvc.y, h0 * Cvc.x);
        p += __shfl_xor_sync(0xffffffffu, p, 4);
        p += __shfl_xor_sync(0xffffffffu, p, 2);
        p += __shfl_xor_sync(0xffffffffu, p, 1);

        if (sp == 0) {
            float yv = fmaf(Dv, xvc, p);
            float sg = __fdividef(1.f, 1.f + __expf(-zvc));
            g_y[yo] = yv * zvc * sg;
        }
        yo += D_INNER;
        dtc = dtn; xvc = xvn; Bvc = Bvn; Cvc = Cvn; zvc = zvn;
    }
}

// ---------------------------------------------------------------------------
// Host side
// ---------------------------------------------------------------------------
extern "C" void kernel_launch(void* const* d_in, const int* in_sizes, int n_in,
                              void* d_out, int out_size)
{
    const float* x          = (const float*)d_in[0];
    const float* in_proj_w  = (const float*)d_in[1];
    const float* conv_w     = (const float*)d_in[2];
    const float* conv_b     = (const float*)d_in[3];
    const float* x_proj_w   = (const float*)d_in[4];
    const float* dt_proj_w  = (const float*)d_in[5];
    const float* dt_proj_b  = (const float*)d_in[6];
    const float* A_log      = (const float*)d_in[7];
    const float* Dp         = (const float*)d_in[8];
    const float* out_proj_w = (const float*)d_in[9];
    float* out = (float*)d_out;

    float *xz, *xc, *xdbl, *dt, *y;
    cudaGetSymbolAddress((void**)&xz,   g_xz);
    cudaGetSymbolAddress((void**)&xc,   g_xc);
    cudaGetSymbolAddress((void**)&xdbl, g_xdbl);
    cudaGetSymbolAddress((void**)&dt,   g_dt);
    cudaGetSymbolAddress((void**)&y,    g_y);
    char *xa,*xb,*w1a,*w1b,*oa,*ob,*ya,*yb;
    float *sx,*sw1,*so,*sy;
    cudaGetSymbolAddress((void**)&xa,  q_xa);  cudaGetSymbolAddress((void**)&xb,  q_xb);
    cudaGetSymbolAddress((void**)&w1a, q_w1a); cudaGetSymbolAddress((void**)&w1b, q_w1b);
    cudaGetSymbolAddress((void**)&oa,  q_oa);  cudaGetSymbolAddress((void**)&ob,  q_ob);
    cudaGetSymbolAddress((void**)&ya,  q_ya);  cudaGetSymbolAddress((void**)&yb,  q_yb);
    cudaGetSymbolAddress((void**)&sx,  g_s_x); cudaGetSymbolAddress((void**)&sw1, g_s_w1);
    cudaGetSymbolAddress((void**)&so,  g_s_o); cudaGetSymbolAddress((void**)&sy,  g_s_y);
    bf16 *xch,*xcl,*xwh,*xwl,*dth,*dtl,*dwh,*dwl;
    cudaGetSymbolAddress((void**)&xch, g_xch); cudaGetSymbolAddress((void**)&xcl, g_xcl);
    cudaGetSymbolAddress((void**)&xwh, g_xwh); cudaGetSymbolAddress((void**)&xwl, g_xwl);
    cudaGetSymbolAddress((void**)&dth, g_dth); cudaGetSymbolAddress((void**)&dtl, g_dtl);
    cudaGetSymbolAddress((void**)&dwh, g_dwh); cudaGetSymbolAddress((void**)&dwl, g_dwl);

    // quantize G1 operands (launches 0-2), then G1 at index 3 (ncu capture slot)
    quant_rows<<<M_TOK, 256>>>(x, D_MODEL, xa, xb, sx);
    quant_rows<<<2*D_INNER, 256>>>(in_proj_w, D_MODEL, w1a, w1b, sw1);
    quant_rows<<<D_MODEL, 256>>>(out_proj_w, D_INNER, oa, ob, so);

    // G1: xz = x @ in_proj_w^T  [4096, 4096], K=1024 (int8x3, warp tile 32x64)
    gemm_imma<128,128,32,64,256><<<dim3(32, 32), 256>>>(
        xa, xb, D_MODEL, w1a, w1b, D_MODEL, sx, sw1, xz, 2*D_INNER, D_MODEL);

    // conv + silu (+ bf16 hi/lo for G2)
    {
        long n = (long)M_TOK * D_INNER;
        conv_silu_kernel<<<(int)((n + 255) / 256), 256>>>(conv_w, conv_b);
    }

    // G2: xdbl = xc @ x_proj_w^T  [4096, 96], K=2048 (bf16x3, BM=32 -> 128 CTAs)
    {
        long n = (long)96 * D_INNER;
        cvt_split<<<(int)((n+255)/256),256>>>(x_proj_w, D_INNER, 11, xwh, xwl, n);
    }
    gemm_mma<32,96,16,48,128,0><<<dim3(1, 128), 128>>>(
        xch, xcl, D_INNER, xwh, xwl, D_INNER, xdbl, 96, D_INNER, nullptr);

    // G3: dt = softplus(dt_lo @ dt_proj_w^T + b)  [4096, 2048], K=64 (bf16x3)
    {
        long n = (long)M_TOK * DT_RANK;
        cvt_split<<<(int)((n+255)/256),256>>>(xdbl, 96, 6, dth, dtl, n);
        n = (long)D_INNER * DT_RANK;
        cvt_split<<<(int)((n+255)/256),256>>>(dt_proj_w, DT_RANK, 6, dwh, dwl, n);
    }
    gemm_mma<128,128,32,32,512,1><<<dim3(16, 32), 512>>>(
        dth, dtl, DT_RANK, dwh, dwl, DT_RANK, dt, D_INNER, DT_RANK, dt_proj_b);

    // selective scan v2 (2 states/thread): 32768 threads
    scan_kernel<<<(M_TOK * D_STATE / 2) / 128, 128>>>(A_log, Dp);

    // quantize y, then G4: out = y @ out_proj_w^T  [4096, 1024], K=2048 (int8x3)
    quant_rows<<<M_TOK, 256>>>(y, D_INNER, ya, yb, sy);
    gemm_imma<128,128,32,64,256><<<dim3(8, 32), 256>>>(
        ya, yb, D_INNER, oa, ob, D_INNER, sy, so, out, D_MODEL, D_INNER);
}

// round 12
// speedup vs baseline: 1.8049x; 1.8049x over previous
#include <cuda_runtime.h>
#include <cuda_bf16.h>
#include <cuda_pipeline.h>
#include <math.h>
#include <stdint.h>

// ---------------------------------------------------------------------------
// Mamba block forward.
// G1/G4: int8x3 IMMA m16n8k32, warp tile 32x32, 512 thr (measured-best R10).
// G2/G3: bf16x3 mma.sync m16n8k16 (R10 configs).
// Scan: chunked linear-recurrence (16 chunks x 128 steps, 3 passes) -> 16x
//       parallelism at 2x work.
// Conservative build: static smem <=48KB, __pipeline intrinsics only.
// ---------------------------------------------------------------------------

#define D_MODEL  1024
#define D_STATE  16
#define D_CONV   4
#define D_INNER  2048
#define DT_RANK  64
#define BATCH    2
#define SEQ      2048
#define M_TOK    (BATCH * SEQ)   // 4096
#define SCHUNK   16
#define SLEN     (SEQ / SCHUNK)  // 128

typedef __nv_bfloat16 bf16;

// fp32 scratch
__device__ float g_xz  [(size_t)M_TOK * 2 * D_INNER];
__device__ float g_xc  [(size_t)M_TOK * D_INNER];
__device__ float g_xdbl[(size_t)M_TOK * 96];
__device__ float g_dt  [(size_t)M_TOK * D_INNER];
__device__ float g_y   [(size_t)M_TOK * D_INNER];

// chunked-scan scratch: [(b*2048+d)*16+s][chunk]
__device__ float g_P [(size_t)M_TOK * D_STATE * SCHUNK / 1];   // decay products
__device__ float g_hl[(size_t)M_TOK * D_STATE * SCHUNK / 1];   // local final h
__device__ float g_hs[(size_t)M_TOK * D_STATE * SCHUNK / 1];   // chunk start h

// int8 operands (+ per-row scales) for G1/G4
__device__ char  q_xa [(size_t)M_TOK * D_MODEL],  q_xb [(size_t)M_TOK * D_MODEL];
__device__ char  q_w1a[(size_t)2*D_INNER*D_MODEL],q_w1b[(size_t)2*D_INNER*D_MODEL];
__device__ char  q_oa [(size_t)D_MODEL * D_INNER],q_ob [(size_t)D_MODEL * D_INNER];
__device__ char  q_ya [(size_t)M_TOK * D_INNER],  q_yb [(size_t)M_TOK * D_INNER];
__device__ float g_s_x[M_TOK], g_s_w1[2*D_INNER], g_s_o[D_MODEL], g_s_y[M_TOK];

// bf16 hi/lo operands for G2/G3
__device__ bf16 g_xch[(size_t)M_TOK * D_INNER],  g_xcl[(size_t)M_TOK * D_INNER];
__device__ bf16 g_xwh[(size_t)96 * D_INNER],     g_xwl[(size_t)96 * D_INNER];
__device__ bf16 g_dth[(size_t)M_TOK * DT_RANK],  g_dtl[(size_t)M_TOK * DT_RANK];
__device__ bf16 g_dwh[(size_t)D_INNER * DT_RANK],g_dwl[(size_t)D_INNER * DT_RANK];

// ---------------------------------------------------------------------------
__device__ __forceinline__ uint32_t smem_u32(const void* p) {
    uint32_t a;
    asm("{ .reg .u64 t; cvta.to.shared.u64 t, %1; cvt.u32.u64 %0, t; }"
        : "=r"(a) : "l"(p));
    return a;
}

#define LDSM4(r0, r1, r2, r3, addr) \
    asm volatile("ldmatrix.sync.aligned.m8n8.x4.shared.b16 {%0,%1,%2,%3}, [%4];" \
        : "=r"(r0), "=r"(r1), "=r"(r2), "=r"(r3) : "r"(addr))

#define MMA_BF16(d, a, b) \
    asm volatile("mma.sync.aligned.m16n8k16.row.col.f32.bf16.bf16.f32 " \
        "{%0,%1,%2,%3}, {%4,%5,%6,%7}, {%8,%9}, {%0,%1,%2,%3};" \
        : "+f"((d)[0]), "+f"((d)[1]), "+f"((d)[2]), "+f"((d)[3]) \
        : "r"((a)[0]), "r"((a)[1]), "r"((a)[2]), "r"((a)[3]), \
          "r"((b)[0]), "r"((b)[1]))

#define MMA_S8(d, a, b) \
    asm volatile("mma.sync.aligned.m16n8k32.row.col.s32.s8.s8.s32 " \
        "{%0,%1,%2,%3}, {%4,%5,%6,%7}, {%8,%9}, {%0,%1,%2,%3};" \
        : "+r"((d)[0]), "+r"((d)[1]), "+r"((d)[2]), "+r"((d)[3]) \
        : "r"((a)[0]), "r"((a)[1]), "r"((a)[2]), "r"((a)[3]), \
          "r"((b)[0]), "r"((b)[1]))

// ---------------------------------------------------------------------------
// int8 GEMM (G1/G4):  C[m,n] = sA[m]*sB[n]*(Q1a.Q1b + (Q2a.Q1b + Q1a.Q2b)/128)
// ---------------------------------------------------------------------------
template<int BM, int BN, int WM, int WN, int THREADS>
__device__ __forceinline__ void stage_load_i8(
    char* sb, const char* a1, const char* a2, int lda,
    const char* b1, const char* b2, int ldb, int koff, int tid)
{
    constexpr int RT = 2 * BM + 2 * BN;
#pragma unroll
    for (int e = tid; e < RT * 2; e += THREADS) {
        const int r = e >> 1, c = e & 1;
        char* dst = sb + (r << 5) + ((c ^ ((r >> 2) & 1)) << 4);
        const char* src;
        if (r < BM)               src = a1 + (long)r * lda + koff + c * 16;
        else if (r < 2 * BM)      src = a2 + (long)(r - BM) * lda + koff + c * 16;
        else if (r < 2 * BM + BN) src = b1 + (long)(r - 2 * BM) * ldb + koff + c * 16;
        else                      src = b2 + (long)(r - 2 * BM - BN) * ldb + koff + c * 16;
        __pipeline_memcpy_async(dst, src, 16);
    }
    __pipeline_commit();
}

template<int BM, int BN, int WM, int WN, int THREADS>
__global__ void __launch_bounds__(THREADS)
gemm_imma(const char* __restrict__ A1, const char* __restrict__ A2, int lda,
          const char* __restrict__ B1, const char* __restrict__ B2, int ldb,
          const float* __restrict__ sA, const float* __restrict__ sB,
          float* __restrict__ C, int ldc, int K)
{
    constexpr int STAGE_B = (2 * BM + 2 * BN) * 32;
    constexpr int WARPS_N = BN / WN;
    constexpr int MA = WM / 16;
    constexpr int NA = WN / 8;

    __shared__ __align__(128) char smem[3 * STAGE_B];

    const int tid = threadIdx.x, wid = tid >> 5, lane = tid & 31;
    const int wm = wid / WARPS_N, wn = wid % WARPS_N;
    const int m0 = blockIdx.y * BM;
    const int n0 = blockIdx.x * BN;
    const int KT = K >> 5;

    const char* a1 = A1 + (long)m0 * lda;
    const char* a2 = A2 + (long)m0 * lda;
    const char* b1 = B1 + (long)n0 * ldb;
    const char* b2 = B2 + (long)n0 * ldb;

    int acc1[MA][NA][4], acc2[MA][NA][4];
#pragma unroll
    for (int i = 0; i < MA; i++)
#pragma unroll
        for (int j = 0; j < NA; j++)
#pragma unroll
            for (int e = 0; e < 4; e++) { acc1[i][j][e] = 0; acc2[i][j][e] = 0; }

    const int a_row  = wm * WM + (lane & 15);
    const int a_csel = lane >> 4;
    const int bg     = lane >> 3;
    const int b_row  = wn * WN + (lane & 7) + ((bg >> 1) << 3);
    const int b_csel = bg & 1;

    const uint32_t s0 = smem_u32(smem);

    stage_load_i8<BM,BN,WM,WN,THREADS>(smem, a1, a2, lda, b1, b2, ldb, 0, tid);
    if (KT > 1)
        stage_load_i8<BM,BN,WM,WN,THREADS>(smem + STAGE_B, a1, a2, lda, b1, b2, ldb, 32, tid);
    else
        __pipeline_commit();

    int cs = 0;
    for (int kt = 0; kt < KT; ++kt) {
        __pipeline_wait_prior(1);
        __syncthreads();

        const uint32_t base = s0 + cs * STAGE_B;
        const uint32_t pA1 = base;
        const uint32_t pA2 = base + BM * 32;
        const uint32_t pB1 = base + 2 * BM * 32;
        const uint32_t pB2 = pB1 + BN * 32;

        uint32_t ar1[MA][4], ar2[MA][4], br1[NA][2], br2[NA][2];
#pragma unroll
        for (int ma = 0; ma < MA; ++ma) {
            const int r = a_row + ma * 16;
            const uint32_t off = r * 32 + ((a_csel ^ ((r >> 2) & 1)) << 4);
            LDSM4(ar1[ma][0], ar1[ma][1], ar1[ma][2], ar1[ma][3], pA1 + off);
            LDSM4(ar2[ma][0], ar2[ma][1], ar2[ma][2], ar2[ma][3], pA2 + off);
        }
#pragma unroll
        for (int p = 0; p < NA / 2; ++p) {
            const int r = b_row + p * 16;
            const uint32_t off = r * 32 + ((b_csel ^ ((r >> 2) & 1)) << 4);
            LDSM4(br1[2*p][0], br1[2*p][1], br1[2*p+1][0], br1[2*p+1][1], pB1 + off);
            LDSM4(br2[2*p][0], br2[2*p][1], br2[2*p+1][0], br2[2*p+1][1], pB2 + off);
        }
#pragma unroll
        for (int ma = 0; ma < MA; ++ma)
#pragma unroll
            for (int na = 0; na < NA; ++na) {
                MMA_S8(acc1[ma][na], ar1[ma], br1[na]);
                MMA_S8(acc2[ma][na], ar2[ma], br1[na]);
                MMA_S8(acc2[ma][na], ar1[ma], br2[na]);
            }

        if (kt + 2 < KT) {
            int ls = cs + 2; if (ls >= 3) ls -= 3;
            stage_load_i8<BM,BN,WM,WN,THREADS>(smem + ls * STAGE_B,
                a1, a2, lda, b1, b2, ldb, (kt + 2) * 32, tid);
        } else {
            __pipeline_commit();
        }
        if (++cs == 3) cs = 0;
    }

    const int er = lane >> 2, ec = (lane & 3) * 2;
#pragma unroll
    for (int ma = 0; ma < MA; ++ma) {
        const int m = m0 + wm * WM + ma * 16 + er;
        const float sa0 = sA[m], sa1 = sA[m + 8];
#pragma unroll
        for (int na = 0; na < NA; ++na) {
            const int n = n0 + wn * WN + na * 8 + ec;
            const float sb0 = sB[n], sb1 = sB[n + 1];
            float2 v0, v1;
            v0.x = sa0 * sb0 * ((float)acc1[ma][na][0] + (float)acc2[ma][na][0] * 0.0078125f);
            v0.y = sa0 * sb1 * ((float)acc1[ma][na][1] + (float)acc2[ma][na][1] * 0.0078125f);
            v1.x = sa1 * sb0 * ((float)acc1[ma][na][2] + (float)acc2[ma][na][2] * 0.0078125f);
            v1.y = sa1 * sb1 * ((float)acc1[ma][na][3] + (float)acc2[ma][na][3] * 0.0078125f);
            *(float2*)(C + (long)m * ldc + n)       = v0;
            *(float2*)(C + (long)(m + 8) * ldc + n) = v1;
        }
    }
}

// ---------------------------------------------------------------------------
// bf16x3 GEMM (G2/G3)
// ---------------------------------------------------------------------------
template<int BM, int BN, int THREADS>
__device__ __forceinline__ void stage_load(
    bf16* sb, const bf16* aH, const bf16* aL, int lda,
    const bf16* bH, const bf16* bL, int ldb, int koff, int tid)
{
    constexpr int RT  = 2 * BM + 2 * BN;
#pragma unroll
    for (int e = tid; e < RT * 2; e += THREADS) {
        const int r = e >> 1, c = e & 1;
        bf16* dst = sb + (r << 4) + ((c ^ ((r >> 2) & 1)) << 3);
        const bf16* src;
        if (r < BM)               src = aH + (long)r * lda + koff + c * 8;
        else if (r < 2 * BM)      src = aL + (long)(r - BM) * lda + koff + c * 8;
        else if (r < 2 * BM + BN) src = bH + (long)(r - 2 * BM) * ldb + koff + c * 8;
        else                      src = bL + (long)(r - 2 * BM - BN) * ldb + koff + c * 8;
        __pipeline_memcpy_async(dst, src, 16);
    }
    __pipeline_commit();
}

template<int BM, int BN, int WM, int WN, int THREADS, int EPI>
__global__ void __launch_bounds__(THREADS)
gemm_mma(const bf16* __restrict__ Ah, const bf16* __restrict__ Al, int lda,
         const bf16* __restrict__ Bh, const bf16* __restrict__ Bl, int ldb,
         float* __restrict__ C, int ldc, int K,
         const float* __restrict__ bias)
{
    constexpr int STAGE_E = (2 * BM + 2 * BN) * 16;
    constexpr int WARPS_N = BN / WN;
    constexpr int MA = WM / 16;
    constexpr int NA = WN / 8;

    __shared__ bf16 smem[3 * STAGE_E];

    const int tid = threadIdx.x, wid = tid >> 5, lane = tid & 31;
    const int wm = wid / WARPS_N, wn = wid % WARPS_N;
    const int m0 = blockIdx.y * BM;
    const int n0 = blockIdx.x * BN;
    const int KT = K >> 4;

    const bf16* aH = Ah + (long)m0 * lda;
    const bf16* aL = Al + (long)m0 * lda;
    const bf16* bH = Bh + (long)n0 * ldb;
    const bf16* bL = Bl + (long)n0 * ldb;

    float acc[MA][NA][4];
#pragma unroll
    for (int i = 0; i < MA; i++)
#pragma unroll
        for (int j = 0; j < NA; j++)
#pragma unroll
            for (int e = 0; e < 4; e++) acc[i][j][e] = 0.f;

    const int a_row  = wm * WM + (lane & 15);
    const int a_csel = lane >> 4;
    const int bg     = lane >> 3;
    const int b_row  = wn * WN + (lane & 7) + ((bg >> 1) << 3);
    const int b_csel = bg & 1;

    const uint32_t s0 = smem_u32(smem);

    stage_load<BM, BN, THREADS>(smem, aH, aL, lda, bH, bL, ldb, 0, tid);
    if (KT > 1)
        stage_load<BM, BN, THREADS>(smem + STAGE_E, aH, aL, lda, bH, bL, ldb, 16, tid);
    else
        __pipeline_commit();

    int cs = 0;
    for (int kt = 0; kt < KT; ++kt) {
        __pipeline_wait_prior(1);
        __syncthreads();

        const uint32_t base = s0 + cs * (STAGE_E * 2);
        const uint32_t pAh = base;
        const uint32_t pAl = base + BM * 32;
        const uint32_t pBh = base + 2 * BM * 32;
        const uint32_t pBl = pBh + BN * 32;

        uint32_t ar[MA][4], alr[MA][4], br[NA][2], blr[NA][2];
#pragma unroll
        for (int ma = 0; ma < MA; ++ma) {
            const int r = a_row + ma * 16;
            const uint32_t off = r * 32 + ((a_csel ^ ((r >> 2) & 1)) << 4);
            LDSM4(ar[ma][0],  ar[ma][1],  ar[ma][2],  ar[ma][3],  pAh + off);
            LDSM4(alr[ma][0], alr[ma][1], alr[ma][2], alr[ma][3], pAl + off);
        }
#pragma unroll
        for (int p = 0; p < NA / 2; ++p) {
            const int r = b_row + p * 16;
            const uint32_t off = r * 32 + ((b_csel ^ ((r >> 2) & 1)) << 4);
            LDSM4(br[2*p][0],  br[2*p][1],  br[2*p+1][0],  br[2*p+1][1],  pBh + off);
            LDSM4(blr[2*p][0], blr[2*p][1], blr[2*p+1][0], blr[2*p+1][1], pBl + off);
        }
#pragma unroll
        for (int ma = 0; ma < MA; ++ma)
#pragma unroll
            for (int na = 0; na < NA; ++na) {
                MMA_BF16(acc[ma][na], ar[ma],  br[na]);
                MMA_BF16(acc[ma][na], alr[ma], br[na]);
                MMA_BF16(acc[ma][na], ar[ma],  blr[na]);
            }

        if (kt + 2 < KT) {
            int ls = cs + 2; if (ls >= 3) ls -= 3;
            stage_load<BM, BN, THREADS>(smem + ls * STAGE_E,
                                        aH, aL, lda, bH, bL, ldb, (kt + 2) * 16, tid);
        } else {
            __pipeline_commit();
        }
        if (++cs == 3) cs = 0;
    }

    const int er = lane >> 2, ec = (lane & 3) * 2;
#pragma unroll
    for (int ma = 0; ma < MA; ++ma) {
#pragma unroll
        for (int na = 0; na < NA; ++na) {
            const int m = m0 + wm * WM + ma * 16 + er;
            const int n = n0 + wn * WN + na * 8 + ec;
            float2 v0 = {acc[ma][na][0], acc[ma][na][1]};
            float2 v1 = {acc[ma][na][2], acc[ma][na][3]};
            if (EPI == 1) {
                const float b0 = bias[n], b1 = bias[n + 1];
                v0.x += b0; v0.y += b1; v1.x += b0; v1.y += b1;
                v0.x = (v0.x > 20.f) ? v0.x : log1pf(__expf(v0.x));
                v0.y = (v0.y > 20.f) ? v0.y : log1pf(__expf(v0.y));
                v1.x = (v1.x > 20.f) ? v1.x : log1pf(__expf(v1.x));
                v1.y = (v1.y > 20.f) ? v1.y : log1pf(__expf(v1.y));
            }
            *(float2*)(C + (long)m * ldc + n)       = v0;
            *(float2*)(C + (long)(m + 8) * ldc + n) = v1;
        }
    }
}

// ---------------------------------------------------------------------------
// Per-row int8x2 quantization
// ---------------------------------------------------------------------------
__global__ void __launch_bounds__(256)
quant_rows(const float* __restrict__ src, int cols,
           char* __restrict__ q1, char* __restrict__ q2,
           float* __restrict__ scale)
{
    __shared__ float red[8];
    const int row = blockIdx.x, tid = threadIdx.x;
    const float* rp = src + (long)row * cols;
    const int nv = cols >> 10;
    float4 v[2];
    float m = 0.f;
    for (int i = 0; i < nv; i++) {
        v[i] = *(const float4*)(rp + tid * 4 + i * 1024);
        m = fmaxf(m, fmaxf(fmaxf(fabsf(v[i].x), fabsf(v[i].y)),
                           fmaxf(fabsf(v[i].z), fabsf(v[i].w))));
    }
    for (int o = 16; o; o >>= 1) m = fmaxf(m, __shfl_xor_sync(0xffffffffu, m, o));
    if ((tid & 31) == 0) red[tid >> 5] = m;
    __syncthreads();
    if (tid < 32) {
        float t = (tid < 8) ? red[tid] : 0.f;
        for (int o = 4; o; o >>= 1) t = fmaxf(t, __shfl_xor_sync(0xffffffffu, t, o));
        if (tid == 0) red[0] = t;
    }
    __syncthreads();
    const float bm  = red[0];
    const float s   = (bm > 1e-30f) ? bm * (1.f / 127.f) : 1.f;
    const float rcp = (bm > 1e-30f) ? 127.f / bm : 0.f;
    for (int i = 0; i < nv; i++) {
        const long o = (long)row * cols + tid * 4 + i * 1024;
        float f[4] = {v[i].x, v[i].y, v[i].z, v[i].w};
        char c1[4], c2[4];
#pragma unroll
        for (int j = 0; j < 4; j++) {
            float t = f[j] * rcp;
            int a = __float2int_rn(t);
            int b = __float2int_rn((t - (float)a) * 128.f);
            c1[j] = (char)a; c2[j] = (char)b;
        }
        *(char4*)(q1 + o) = make_char4(c1[0], c1[1], c1[2], c1[3]);
        *(char4*)(q2 + o) = make_char4(c2[0], c2[1], c2[2], c2[3]);
    }
    if (tid == 0) scale[row] = s;
}

// ---------------------------------------------------------------------------
__global__ void cvt_split(const float* __restrict__ src, int ld, int lc,
                          bf16* __restrict__ hi, bf16* __restrict__ lo, long total)
{
    long i = (long)blockIdx.x * blockDim.x + threadIdx.x;
    if (i >= total) return;
    long r = i >> lc;
    int c = (int)(i & ((1 << lc) - 1));
    float v = src[r * ld + c];
    bf16 h = __float2bfloat16(v);
    hi[i] = h;
    lo[i] = __float2bfloat16(v - __bfloat162float(h));
}

// ---------------------------------------------------------------------------
__global__ void conv_silu_kernel(const float* __restrict__ conv_w,
                                 const float* __restrict__ conv_b)
{
    long idx = (long)blockIdx.x * blockDim.x + threadIdx.x;
    if (idx >= (long)M_TOK * D_INNER) return;
    int d = (int)(idx & (D_INNER - 1));
    long m = idx >> 11;
    int t = (int)(m & (SEQ - 1));
    long row0 = m - t;

    float acc = conv_b[d];
    const float* w = conv_w + d * 4;
#pragma unroll
    for (int j = 0; j < D_CONV; j++) {
        int tt = t - (D_CONV - 1) + j;
        if (tt >= 0)
            acc = fmaf(g_xz[(row0 + tt) * (2 * D_INNER) + d], w[j], acc);
    }
    float s = __fdividef(1.f, 1.f + __expf(-acc));
    float v = acc * s;
    long o = m * D_INNER + d;
    g_xc[o] = v;
    bf16 h = __float2bfloat16(v);
    g_xch[o] = h;
    g_xcl[o] = __float2bfloat16(v - __bfloat162float(h));
}

// ---------------------------------------------------------------------------
// Chunked scan, pass 1: per (b,d,s,chunk) compute decay product P and
// zero-start local state h_l over SLEN steps.
// ---------------------------------------------------------------------------
__global__ void __launch_bounds__(128)
scan_pass1(const float* __restrict__ A_log)
{
    int tid = blockIdx.x * 128 + threadIdx.x;
    int s  = tid & 15;
    int ck = (tid >> 4) & (SCHUNK - 1);
    int c  = tid >> 8;               // (b,d): 0..4095
    int d  = c & (D_INNER - 1);
    int b  = c >> 11;

    const float a = -__expf(A_log[d * D_STATE + s]);
    const int t0 = ck * SLEN;
    const float* dt_p = g_dt   + ((long)b * SEQ + t0) * D_INNER + d;
    const float* xc_p = g_xc   + ((long)b * SEQ + t0) * D_INNER + d;
    const float* bc_p = g_xdbl + ((long)b * SEQ + t0) * 96 + DT_RANK + s;

    float h = 0.f, P = 1.f;
#pragma unroll 4
    for (int t = 0; t < SLEN; t++) {
        float dt = __ldg(dt_p);
        float xv = __ldg(xc_p);
        float Bv = __ldg(bc_p);
        float dA = __expf(dt * a);
        h = fmaf(dA, h, dt * Bv * xv);
        P *= dA;
        dt_p += D_INNER; xc_p += D_INNER; bc_p += 96;
    }
    long o = ((long)c * D_STATE + s) * SCHUNK + ck;
    g_P[o] = P; g_hl[o] = h;
}

// ---------------------------------------------------------------------------
// Pass 2: sequential chunk prefix per (b,d,s): hs[0]=0; hs[i+1]=P[i]*hs[i]+hl[i]
// ---------------------------------------------------------------------------
__global__ void __launch_bounds__(256)
scan_pass2()
{
    int i = blockIdx.x * 256 + threadIdx.x;       // 0..65535
    long base = (long)i * SCHUNK;
    float hs = 0.f;
#pragma unroll
    for (int ck = 0; ck < SCHUNK; ck++) {
        g_hs[base + ck] = hs;
        hs = fmaf(g_P[base + ck], hs, g_hl[base + ck]);
    }
}

// ---------------------------------------------------------------------------
// Pass 3: re-run each chunk from correct start state; 16-lane reduce; emit y.
// ---------------------------------------------------------------------------
__global__ void __launch_bounds__(128)
scan_pass3(const float* __restrict__ A_log, const float* __restrict__ Dp)
{
    int tid = blockIdx.x * 128 + threadIdx.x;
    int s  = tid & 15;
    int ck = (tid >> 4) & (SCHUNK - 1);
    int c  = tid >> 8;
    int d  = c & (D_INNER - 1);
    int b  = c >> 11;

    const float a  = -__expf(A_log[d * D_STATE + s]);
    const float Dv = Dp[d];
    float h = g_hs[((long)c * D_STATE + s) * SCHUNK + ck];

    const int t0 = ck * SLEN;
    const float* dt_p = g_dt   + ((long)b * SEQ + t0) * D_INNER + d;
    const float* xc_p = g_xc   + ((long)b * SEQ + t0) * D_INNER + d;
    const float* z_p  = g_xz   + ((long)b * SEQ + t0) * (2 * D_INNER) + D_INNER + d;
    const float* bc_p = g_xdbl + ((long)b * SEQ + t0) * 96 + DT_RANK + s;
    long yo = ((long)b * SEQ + t0) * D_INNER + d;

#pragma unroll 2
    for (int t = 0; t < SLEN; t++) {
        float dt = __ldg(dt_p);
        float xv = __ldg(xc_p);
        float Bv = __ldg(bc_p);
        float Cv = __ldg(bc_p + D_STATE);

        float dA = __expf(dt * a);
        h = fmaf(dA, h, dt * Bv * xv);

        float p = h * Cv;
        p += __shfl_xor_sync(0xffffffffu, p, 8);
        p += __shfl_xor_sync(0xffffffffu, p, 4);
        p += __shfl_xor_sync(0xffffffffu, p, 2);
        p += __shfl_xor_sync(0xffffffffu, p, 1);

        if (s == 0) {
            float z  = __ldg(z_p);
            float yv = fmaf(Dv, xv, p);
            float sg = __fdividef(1.f, 1.f + __expf(-z));
            g_y[yo] = yv * z * sg;
        }
        dt_p += D_INNER; xc_p += D_INNER; z_p += 2 * D_INNER; bc_p += 96;
        yo += D_INNER;
    }
}

// ---------------------------------------------------------------------------
// Host side
// ---------------------------------------------------------------------------
extern "C" void kernel_launch(void* const* d_in, const int* in_sizes, int n_in,
                              void* d_out, int out_size)
{
    const float* x          = (const float*)d_in[0];
    const float* in_proj_w  = (const float*)d_in[1];
    const float* conv_w     = (const float*)d_in[2];
    const float* conv_b     = (const float*)d_in[3];
    const float* x_proj_w   = (const float*)d_in[4];
    const float* dt_proj_w  = (const float*)d_in[5];
    const float* dt_proj_b  = (const float*)d_in[6];
    const float* A_log      = (const float*)d_in[7];
    const float* Dp         = (const float*)d_in[8];
    const float* out_proj_w = (const float*)d_in[9];
    float* out = (float*)d_out;

    float *xz, *xc, *xdbl, *dt, *y;
    cudaGetSymbolAddress((void**)&xz,   g_xz);
    cudaGetSymbolAddress((void**)&xc,   g_xc);
    cudaGetSymbolAddress((void**)&xdbl, g_xdbl);
    cudaGetSymbolAddress((void**)&dt,   g_dt);
    cudaGetSymbolAddress((void**)&y,    g_y);
    char *xa,*xb,*w1a,*w1b,*oa,*ob,*ya,*yb;
    float *sx,*sw1,*so,*sy;
    cudaGetSymbolAddress((void**)&xa,  q_xa);  cudaGetSymbolAddress((void**)&xb,  q_xb);
    cudaGetSymbolAddress((void**)&w1a, q_w1a); cudaGetSymbolAddress((void**)&w1b, q_w1b);
    cudaGetSymbolAddress((void**)&oa,  q_oa);  cudaGetSymbolAddress((void**)&ob,  q_ob);
    cudaGetSymbolAddress((void**)&ya,  q_ya);  cudaGetSymbolAddress((void**)&yb,  q_yb);
    cudaGetSymbolAddress((void**)&sx,  g_s_x); cudaGetSymbolAddress((void**)&sw1, g_s_w1);
    cudaGetSymbolAddress((void**)&so,  g_s_o); cudaGetSymbolAddress((void**)&sy,  g_s_y);
    bf16 *xch,*xcl,*xwh,*xwl,*dth,*dtl,*dwh,*dwl;
    cudaGetSymbolAddress((void**)&xch, g_xch); cudaGetSymbolAddress((void**)&xcl, g_xcl);
    cudaGetSymbolAddress((void**)&xwh, g_xwh); cudaGetSymbolAddress((void**)&xwl, g_xwl);
    cudaGetSymbolAddress((void**)&dth, g_dth); cudaGetSymbolAddress((void**)&dtl, g_dtl);
    cudaGetSymbolAddress((void**)&dwh, g_dwh); cudaGetSymbolAddress((void**)&dwl, g_dwl);

    // quantize G1 operands (launches 0-2), then G1 at index 3 (ncu capture slot)
    quant_rows<<<M_TOK, 256>>>(x, D_MODEL, xa, xb, sx);
    quant_rows<<<2*D_INNER, 256>>>(in_proj_w, D_MODEL, w1a, w1b, sw1);
    quant_rows<<<D_MODEL, 256>>>(out_proj_w, D_INNER, oa, ob, so);

    // G1: xz = x @ in_proj_w^T  [4096, 4096], K=1024 (int8x3, R10 config)
    gemm_imma<128,128,32,32,512><<<dim3(32, 32), 512>>>(
        xa, xb, D_MODEL, w1a, w1b, D_MODEL, sx, sw1, xz, 2*D_INNER, D_MODEL);

    // conv + silu (+ bf16 hi/lo for G2)
    {
        long n = (long)M_TOK * D_INNER;
        conv_silu_kernel<<<(int)((n + 255) / 256), 256>>>(conv_w, conv_b);
    }

    // G2: xdbl = xc @ x_proj_w^T  [4096, 96], K=2048 (bf16x3, R10 config)
    {
        long n = (long)96 * D_INNER;
        cvt_split<<<(int)((n+255)/256),256>>>(x_proj_w, D_INNER, 11, xwh, xwl, n);
    }
    gemm_mma<64,96,16,48,256,0><<<dim3(1, 64), 256>>>(
        xch, xcl, D_INNER, xwh, xwl, D_INNER, xdbl, 96, D_INNER, nullptr);

    // G3: dt = softplus(dt_lo @ dt_proj_w^T + b)  [4096, 2048], K=64 (bf16x3)
    {
        long n = (long)M_TOK * DT_RANK;
        cvt_split<<<(int)((n+255)/256),256>>>(xdbl, 96, 6, dth, dtl, n);
        n = (long)D_INNER * DT_RANK;
        cvt_split<<<(int)((n+255)/256),256>>>(dt_proj_w, DT_RANK, 6, dwh, dwl, n);
    }
    gemm_mma<128,128,32,32,512,1><<<dim3(16, 32), 512>>>(
        dth, dtl, DT_RANK, dwh, dwl, DT_RANK, dt, D_INNER, DT_RANK, dt_proj_b);

    // chunked selective scan: 16x parallelism
    scan_pass1<<<(M_TOK * D_STATE * SCHUNK) / 128, 128>>>(A_log);
    scan_pass2<<<(M_TOK * D_STATE) / 256, 256>>>();
    scan_pass3<<<(M_TOK * D_STATE * SCHUNK) / 128, 128>>>(A_log, Dp);

    // quantize y, then G4: out = y @ out_proj_w^T  [4096, 1024], K=2048 (int8x3)
    quant_rows<<<M_TOK, 256>>>(y, D_INNER, ya, yb, sy);
    gemm_imma<128,128,32,32,512><<<dim3(8, 32), 512>>>(
        ya, yb, D_INNER, oa, ob, D_INNER, sy, so, out, D_MODEL, D_INNER);
}

// round 13
// speedup vs baseline: 2.0433x; 1.1321x over previous
#include <cuda_runtime.h>
#include <cuda_bf16.h>
#include <cuda_pipeline.h>
#include <math.h>
#include <stdint.h>

// ---------------------------------------------------------------------------
// Mamba block forward.
// G1/G4: int8x3 IMMA m16n8k32, warp tile 32x32, 512 thr (measured-best).
// G2/G3: bf16x3 mma.sync m16n8k16.
// Scan: chunked linear-recurrence (16 chunks x 128 steps, 3 passes),
//       2 states per thread (float2 B/C, 3-shfl reduce) -> fewer LDG/SHFL.
// Conservative build: static smem <=48KB, __pipeline intrinsics only.
// ---------------------------------------------------------------------------

#define D_MODEL  1024
#define D_STATE  16
#define D_CONV   4
#define D_INNER  2048
#define DT_RANK  64
#define BATCH    2
#define SEQ      2048
#define M_TOK    (BATCH * SEQ)   // 4096
#define SCHUNK   16
#define SLEN     (SEQ / SCHUNK)  // 128

typedef __nv_bfloat16 bf16;

// fp32 scratch
__device__ float g_xz  [(size_t)M_TOK * 2 * D_INNER];
__device__ float g_xc  [(size_t)M_TOK * D_INNER];
__device__ float g_xdbl[(size_t)M_TOK * 96];
__device__ float g_dt  [(size_t)M_TOK * D_INNER];
__device__ float g_y   [(size_t)M_TOK * D_INNER];

// chunked-scan scratch: [(c*16+s)*16+ck]
__device__ float g_P [(size_t)M_TOK * D_STATE * SCHUNK];
__device__ float g_hl[(size_t)M_TOK * D_STATE * SCHUNK];
__device__ float g_hs[(size_t)M_TOK * D_STATE * SCHUNK];

// int8 operands (+ per-row scales) for G1/G4
__device__ char  q_xa [(size_t)M_TOK * D_MODEL],  q_xb [(size_t)M_TOK * D_MODEL];
__device__ char  q_w1a[(size_t)2*D_INNER*D_MODEL],q_w1b[(size_t)2*D_INNER*D_MODEL];
__device__ char  q_oa [(size_t)D_MODEL * D_INNER],q_ob [(size_t)D_MODEL * D_INNER];
__device__ char  q_ya [(size_t)M_TOK * D_INNER],  q_yb [(size_t)M_TOK * D_INNER];
__device__ float g_s_x[M_TOK], g_s_w1[2*D_INNER], g_s_o[D_MODEL], g_s_y[M_TOK];

// bf16 hi/lo operands for G2/G3
__device__ bf16 g_xch[(size_t)M_TOK * D_INNER],  g_xcl[(size_t)M_TOK * D_INNER];
__device__ bf16 g_xwh[(size_t)96 * D_INNER],     g_xwl[(size_t)96 * D_INNER];
__device__ bf16 g_dth[(size_t)M_TOK * DT_RANK],  g_dtl[(size_t)M_TOK * DT_RANK];
__device__ bf16 g_dwh[(size_t)D_INNER * DT_RANK],g_dwl[(size_t)D_INNER * DT_RANK];

// ---------------------------------------------------------------------------
__device__ __forceinline__ uint32_t smem_u32(const void* p) {
    uint32_t a;
    asm("{ .reg .u64 t; cvta.to.shared.u64 t, %1; cvt.u32.u64 %0, t; }"
        : "=r"(a) : "l"(p));
    return a;
}

#define LDSM4(r0, r1, r2, r3, addr) \
    asm volatile("ldmatrix.sync.aligned.m8n8.x4.shared.b16 {%0,%1,%2,%3}, [%4];" \
        : "=r"(r0), "=r"(r1), "=r"(r2), "=r"(r3) : "r"(addr))

#define MMA_BF16(d, a, b) \
    asm volatile("mma.sync.aligned.m16n8k16.row.col.f32.bf16.bf16.f32 " \
        "{%0,%1,%2,%3}, {%4,%5,%6,%7}, {%8,%9}, {%0,%1,%2,%3};" \
        : "+f"((d)[0]), "+f"((d)[1]), "+f"((d)[2]), "+f"((d)[3]) \
        : "r"((a)[0]), "r"((a)[1]), "r"((a)[2]), "r"((a)[3]), \
          "r"((b)[0]), "r"((b)[1]))

#define MMA_S8(d, a, b) \
    asm volatile("mma.sync.aligned.m16n8k32.row.col.s32.s8.s8.s32 " \
        "{%0,%1,%2,%3}, {%4,%5,%6,%7}, {%8,%9}, {%0,%1,%2,%3};" \
        : "+r"((d)[0]), "+r"((d)[1]), "+r"((d)[2]), "+r"((d)[3]) \
        : "r"((a)[0]), "r"((a)[1]), "r"((a)[2]), "r"((a)[3]), \
          "r"((b)[0]), "r"((b)[1]))

// ---------------------------------------------------------------------------
// int8 GEMM (G1/G4):  C[m,n] = sA[m]*sB[n]*(Q1a.Q1b + (Q2a.Q1b + Q1a.Q2b)/128)
// ---------------------------------------------------------------------------
template<int BM, int BN, int WM, int WN, int THREADS>
__device__ __forceinline__ void stage_load_i8(
    char* sb, const char* a1, const char* a2, int lda,
    const char* b1, const char* b2, int ldb, int koff, int tid)
{
    constexpr int RT = 2 * BM + 2 * BN;
#pragma unroll
    for (int e = tid; e < RT * 2; e += THREADS) {
        const int r = e >> 1, c = e & 1;
        char* dst = sb + (r << 5) + ((c ^ ((r >> 2) & 1)) << 4);
        const char* src;
        if (r < BM)               src = a1 + (long)r * lda + koff + c * 16;
        else if (r < 2 * BM)      src = a2 + (long)(r - BM) * lda + koff + c * 16;
        else if (r < 2 * BM + BN) src = b1 + (long)(r - 2 * BM) * ldb + koff + c * 16;
        else                      src = b2 + (long)(r - 2 * BM - BN) * ldb + koff + c * 16;
        __pipeline_memcpy_async(dst, src, 16);
    }
    __pipeline_commit();
}

template<int BM, int BN, int WM, int WN, int THREADS>
__global__ void __launch_bounds__(THREADS)
gemm_imma(const char* __restrict__ A1, const char* __restrict__ A2, int lda,
          const char* __restrict__ B1, const char* __restrict__ B2, int ldb,
          const float* __restrict__ sA, const float* __restrict__ sB,
          float* __restrict__ C, int ldc, int K)
{
    constexpr int STAGE_B = (2 * BM + 2 * BN) * 32;
    constexpr int WARPS_N = BN / WN;
    constexpr int MA = WM / 16;
    constexpr int NA = WN / 8;

    __shared__ __align__(128) char smem[3 * STAGE_B];

    const int tid = threadIdx.x, wid = tid >> 5, lane = tid & 31;
    const int wm = wid / WARPS_N, wn = wid % WARPS_N;
    const int m0 = blockIdx.y * BM;
    const int n0 = blockIdx.x * BN;
    const int KT = K >> 5;

    const char* a1 = A1 + (long)m0 * lda;
    const char* a2 = A2 + (long)m0 * lda;
    const char* b1 = B1 + (long)n0 * ldb;
    const char* b2 = B2 + (long)n0 * ldb;

    int acc1[MA][NA][4], acc2[MA][NA][4];
#pragma unroll
    for (int i = 0; i < MA; i++)
#pragma unroll
        for (int j = 0; j < NA; j++)
#pragma unroll
            for (int e = 0; e < 4; e++) { acc1[i][j][e] = 0; acc2[i][j][e] = 0; }

    const int a_row  = wm * WM + (lane & 15);
    const int a_csel = lane >> 4;
    const int bg     = lane >> 3;
    const int b_row  = wn * WN + (lane & 7) + ((bg >> 1) << 3);
    const int b_csel = bg & 1;

    const uint32_t s0 = smem_u32(smem);

    stage_load_i8<BM,BN,WM,WN,THREADS>(smem, a1, a2, lda, b1, b2, ldb, 0, tid);
    if (KT > 1)
        stage_load_i8<BM,BN,WM,WN,THREADS>(smem + STAGE_B, a1, a2, lda, b1, b2, ldb, 32, tid);
    else
        __pipeline_commit();

    int cs = 0;
    for (int kt = 0; kt < KT; ++kt) {
        __pipeline_wait_prior(1);
        __syncthreads();

        const uint32_t base = s0 + cs * STAGE_B;
        const uint32_t pA1 = base;
        const uint32_t pA2 = base + BM * 32;
        const uint32_t pB1 = base + 2 * BM * 32;
        const uint32_t pB2 = pB1 + BN * 32;

        uint32_t ar1[MA][4], ar2[MA][4], br1[NA][2], br2[NA][2];
#pragma unroll
        for (int ma = 0; ma < MA; ++ma) {
            const int r = a_row + ma * 16;
            const uint32_t off = r * 32 + ((a_csel ^ ((r >> 2) & 1)) << 4);
            LDSM4(ar1[ma][0], ar1[ma][1], ar1[ma][2], ar1[ma][3], pA1 + off);
            LDSM4(ar2[ma][0], ar2[ma][1], ar2[ma][2], ar2[ma][3], pA2 + off);
        }
#pragma unroll
        for (int p = 0; p < NA / 2; ++p) {
            const int r = b_row + p * 16;
            const uint32_t off = r * 32 + ((b_csel ^ ((r >> 2) & 1)) << 4);
            LDSM4(br1[2*p][0], br1[2*p][1], br1[2*p+1][0], br1[2*p+1][1], pB1 + off);
            LDSM4(br2[2*p][0], br2[2*p][1], br2[2*p+1][0], br2[2*p+1][1], pB2 + off);
        }
#pragma unroll
        for (int ma = 0; ma < MA; ++ma)
#pragma unroll
            for (int na = 0; na < NA; ++na) {
                MMA_S8(acc1[ma][na], ar1[ma], br1[na]);
                MMA_S8(acc2[ma][na], ar2[ma], br1[na]);
                MMA_S8(acc2[ma][na], ar1[ma], br2[na]);
            }

        if (kt + 2 < KT) {
            int ls = cs + 2; if (ls >= 3) ls -= 3;
            stage_load_i8<BM,BN,WM,WN,THREADS>(smem + ls * STAGE_B,
                a1, a2, lda, b1, b2, ldb, (kt + 2) * 32, tid);
        } else {
            __pipeline_commit();
        }
        if (++cs == 3) cs = 0;
    }

    const int er = lane >> 2, ec = (lane & 3) * 2;
#pragma unroll
    for (int ma = 0; ma < MA; ++ma) {
        const int m = m0 + wm * WM + ma * 16 + er;
        const float sa0 = sA[m], sa1 = sA[m + 8];
#pragma unroll
        for (int na = 0; na < NA; ++na) {
            const int n = n0 + wn * WN + na * 8 + ec;
            const float sb0 = sB[n], sb1 = sB[n + 1];
            float2 v0, v1;
            v0.x = sa0 * sb0 * ((float)acc1[ma][na][0] + (float)acc2[ma][na][0] * 0.0078125f);
            v0.y = sa0 * sb1 * ((float)acc1[ma][na][1] + (float)acc2[ma][na][1] * 0.0078125f);
            v1.x = sa1 * sb0 * ((float)acc1[ma][na][2] + (float)acc2[ma][na][2] * 0.0078125f);
            v1.y = sa1 * sb1 * ((float)acc1[ma][na][3] + (float)acc2[ma][na][3] * 0.0078125f);
            *(float2*)(C + (long)m * ldc + n)       = v0;
            *(float2*)(C + (long)(m + 8) * ldc + n) = v1;
        }
    }
}

// ---------------------------------------------------------------------------
// bf16x3 GEMM (G2/G3)
// ---------------------------------------------------------------------------
template<int BM, int BN, int THREADS>
__device__ __forceinline__ void stage_load(
    bf16* sb, const bf16* aH, const bf16* aL, int lda,
    const bf16* bH, const bf16* bL, int ldb, int koff, int tid)
{
    constexpr int RT  = 2 * BM + 2 * BN;
#pragma unroll
    for (int e = tid; e < RT * 2; e += THREADS) {
        const int r = e >> 1, c = e & 1;
        bf16* dst = sb + (r << 4) + ((c ^ ((r >> 2) & 1)) << 3);
        const bf16* src;
        if (r < BM)               src = aH + (long)r * lda + koff + c * 8;
        else if (r < 2 * BM)      src = aL + (long)(r - BM) * lda + koff + c * 8;
        else if (r < 2 * BM + BN) src = bH + (long)(r - 2 * BM) * ldb + koff + c * 8;
        else                      src = bL + (long)(r - 2 * BM - BN) * ldb + koff + c * 8;
        __pipeline_memcpy_async(dst, src, 16);
    }
    __pipeline_commit();
}

template<int BM, int BN, int WM, int WN, int THREADS, int EPI>
__global__ void __launch_bounds__(THREADS)
gemm_mma(const bf16* __restrict__ Ah, const bf16* __restrict__ Al, int lda,
         const bf16* __restrict__ Bh, const bf16* __restrict__ Bl, int ldb,
         float* __restrict__ C, int ldc, int K,
         const float* __restrict__ bias)
{
    constexpr int STAGE_E = (2 * BM + 2 * BN) * 16;
    constexpr int WARPS_N = BN / WN;
    constexpr int MA = WM / 16;
    constexpr int NA = WN / 8;

    __shared__ bf16 smem[3 * STAGE_E];

    const int tid = threadIdx.x, wid = tid >> 5, lane = tid & 31;
    const int wm = wid / WARPS_N, wn = wid % WARPS_N;
    const int m0 = blockIdx.y * BM;
    const int n0 = blockIdx.x * BN;
    const int KT = K >> 4;

    const bf16* aH = Ah + (long)m0 * lda;
    const bf16* aL = Al + (long)m0 * lda;
    const bf16* bH = Bh + (long)n0 * ldb;
    const bf16* bL = Bl + (long)n0 * ldb;

    float acc[MA][NA][4];
#pragma unroll
    for (int i = 0; i < MA; i++)
#pragma unroll
        for (int j = 0; j < NA; j++)
#pragma unroll
            for (int e = 0; e < 4; e++) acc[i][j][e] = 0.f;

    const int a_row  = wm * WM + (lane & 15);
    const int a_csel = lane >> 4;
    const int bg     = lane >> 3;
    const int b_row  = wn * WN + (lane & 7) + ((bg >> 1) << 3);
    const int b_csel = bg & 1;

    const uint32_t s0 = smem_u32(smem);

    stage_load<BM, BN, THREADS>(smem, aH, aL, lda, bH, bL, ldb, 0, tid);
    if (KT > 1)
        stage_load<BM, BN, THREADS>(smem + STAGE_E, aH, aL, lda, bH, bL, ldb, 16, tid);
    else
        __pipeline_commit();

    int cs = 0;
    for (int kt = 0; kt < KT; ++kt) {
        __pipeline_wait_prior(1);
        __syncthreads();

        const uint32_t base = s0 + cs * (STAGE_E * 2);
        const uint32_t pAh = base;
        const uint32_t pAl = base + BM * 32;
        const uint32_t pBh = base + 2 * BM * 32;
        const uint32_t pBl = pBh + BN * 32;

        uint32_t ar[MA][4], alr[MA][4], br[NA][2], blr[NA][2];
#pragma unroll
        for (int ma = 0; ma < MA; ++ma) {
            const int r = a_row + ma * 16;
            const uint32_t off = r * 32 + ((a_csel ^ ((r >> 2) & 1)) << 4);
            LDSM4(ar[ma][0],  ar[ma][1],  ar[ma][2],  ar[ma][3],  pAh + off);
            LDSM4(alr[ma][0], alr[ma][1], alr[ma][2], alr[ma][3], pAl + off);
        }
#pragma unroll
        for (int p = 0; p < NA / 2; ++p) {
            const int r = b_row + p * 16;
            const uint32_t off = r * 32 + ((b_csel ^ ((r >> 2) & 1)) << 4);
            LDSM4(br[2*p][0],  br[2*p][1],  br[2*p+1][0],  br[2*p+1][1],  pBh + off);
            LDSM4(blr[2*p][0], blr[2*p][1], blr[2*p+1][0], blr[2*p+1][1], pBl + off);
        }
#pragma unroll
        for (int ma = 0; ma < MA; ++ma)
#pragma unroll
            for (int na = 0; na < NA; ++na) {
                MMA_BF16(acc[ma][na], ar[ma],  br[na]);
                MMA_BF16(acc[ma][na], alr[ma], br[na]);
                MMA_BF16(acc[ma][na], ar[ma],  blr[na]);
            }

        if (kt + 2 < KT) {
            int ls = cs + 2; if (ls >= 3) ls -= 3;
            stage_load<BM, BN, THREADS>(smem + ls * STAGE_E,
                                        aH, aL, lda, bH, bL, ldb, (kt + 2) * 16, tid);
        } else {
            __pipeline_commit();
        }
        if (++cs == 3) cs = 0;
    }

    const int er = lane >> 2, ec = (lane & 3) * 2;
#pragma unroll
    for (int ma = 0; ma < MA; ++ma) {
#pragma unroll
        for (int na = 0; na < NA; ++na) {
            const int m = m0 + wm * WM + ma * 16 + er;
            const int n = n0 + wn * WN + na * 8 + ec;
            float2 v0 = {acc[ma][na][0], acc[ma][na][1]};
            float2 v1 = {acc[ma][na][2], acc[ma][na][3]};
            if (EPI == 1) {
                const float b0 = bias[n], b1 = bias[n + 1];
                v0.x += b0; v0.y += b1; v1.x += b0; v1.y += b1;
                v0.x = (v0.x > 20.f) ? v0.x : log1pf(__expf(v0.x));
                v0.y = (v0.y > 20.f) ? v0.y : log1pf(__expf(v0.y));
                v1.x = (v1.x > 20.f) ? v1.x : log1pf(__expf(v1.x));
                v1.y = (v1.y > 20.f) ? v1.y : log1pf(__expf(v1.y));
            }
            *(float2*)(C + (long)m * ldc + n)       = v0;
            *(float2*)(C + (long)(m + 8) * ldc + n) = v1;
        }
    }
}

// ---------------------------------------------------------------------------
// Per-row int8x2 quantization
// ---------------------------------------------------------------------------
__global__ void __launch_bounds__(256)
quant_rows(const float* __restrict__ src, int cols,
           char* __restrict__ q1, char* __restrict__ q2,
           float* __restrict__ scale)
{
    __shared__ float red[8];
    const int row = blockIdx.x, tid = threadIdx.x;
    const float* rp = src + (long)row * cols;
    const int nv = cols >> 10;
    float4 v[2];
    float m = 0.f;
    for (int i = 0; i < nv; i++) {
        v[i] = *(const float4*)(rp + tid * 4 + i * 1024);
        m = fmaxf(m, fmaxf(fmaxf(fabsf(v[i].x), fabsf(v[i].y)),
                           fmaxf(fabsf(v[i].z), fabsf(v[i].w))));
    }
    for (int o = 16; o; o >>= 1) m = fmaxf(m, __shfl_xor_sync(0xffffffffu, m, o));
    if ((tid & 31) == 0) red[tid >> 5] = m;
    __syncthreads();
    if (tid < 32) {
        float t = (tid < 8) ? red[tid] : 0.f;
        for (int o = 4; o; o >>= 1) t = fmaxf(t, __shfl_xor_sync(0xffffffffu, t, o));
        if (tid == 0) red[0] = t;
    }
    __syncthreads();
    const float bm  = red[0];
    const float s   = (bm > 1e-30f) ? bm * (1.f / 127.f) : 1.f;
    const float rcp = (bm > 1e-30f) ? 127.f / bm : 0.f;
    for (int i = 0; i < nv; i++) {
        const long o = (long)row * cols + tid * 4 + i * 1024;
        float f[4] = {v[i].x, v[i].y, v[i].z, v[i].w};
        char c1[4], c2[4];
#pragma unroll
        for (int j = 0; j < 4; j++) {
            float t = f[j] * rcp;
            int a = __float2int_rn(t);
            int b = __float2int_rn((t - (float)a) * 128.f);
            c1[j] = (char)a; c2[j] = (char)b;
        }
        *(char4*)(q1 + o) = make_char4(c1[0], c1[1], c1[2], c1[3]);
        *(char4*)(q2 + o) = make_char4(c2[0], c2[1], c2[2], c2[3]);
    }
    if (tid == 0) scale[row] = s;
}

// ---------------------------------------------------------------------------
__global__ void cvt_split(const float* __restrict__ src, int ld, int lc,
                          bf16* __restrict__ hi, bf16* __restrict__ lo, long total)
{
    long i = (long)blockIdx.x * blockDim.x + threadIdx.x;
    if (i >= total) return;
    long r = i >> lc;
    int c = (int)(i & ((1 << lc) - 1));
    float v = src[r * ld + c];
    bf16 h = __float2bfloat16(v);
    hi[i] = h;
    lo[i] = __float2bfloat16(v - __bfloat162float(h));
}

// ---------------------------------------------------------------------------
__global__ void conv_silu_kernel(const float* __restrict__ conv_w,
                                 const float* __restrict__ conv_b)
{
    long idx = (long)blockIdx.x * blockDim.x + threadIdx.x;
    if (idx >= (long)M_TOK * D_INNER) return;
    int d = (int)(idx & (D_INNER - 1));
    long m = idx >> 11;
    int t = (int)(m & (SEQ - 1));
    long row0 = m - t;

    float acc = conv_b[d];
    const float* w = conv_w + d * 4;
#pragma unroll
    for (int j = 0; j < D_CONV; j++) {
        int tt = t - (D_CONV - 1) + j;
        if (tt >= 0)
            acc = fmaf(g_xz[(row0 + tt) * (2 * D_INNER) + d], w[j], acc);
    }
    float s = __fdividef(1.f, 1.f + __expf(-acc));
    float v = acc * s;
    long o = m * D_INNER + d;
    g_xc[o] = v;
    bf16 h = __float2bfloat16(v);
    g_xch[o] = h;
    g_xcl[o] = __float2bfloat16(v - __bfloat162float(h));
}

// ---------------------------------------------------------------------------
// Chunked scan pass 1, 2 states/thread: per (c, ck, sp) compute decay
// products P and zero-start local states over SLEN steps.
// tid: sp = tid&7, ck = (tid>>3)&15, c = tid>>7.
// ---------------------------------------------------------------------------
__global__ void __launch_bounds__(128)
scan_pass1(const float* __restrict__ A_log)
{
    int tid = blockIdx.x * 128 + threadIdx.x;
    int sp = tid & 7;
    int ck = (tid >> 3) & (SCHUNK - 1);
    int c  = tid >> 7;               // (b,d): 0..4095
    int d  = c & (D_INNER - 1);
    int b  = c >> 11;
    int si = sp * 2;

    const float a0 = -__expf(A_log[d * D_STATE + si]);
    const float a1 = -__expf(A_log[d * D_STATE + si + 1]);
    const int t0 = ck * SLEN;
    const float* dt_p = g_dt   + ((long)b * SEQ + t0) * D_INNER + d;
    const float* xc_p = g_xc   + ((long)b * SEQ + t0) * D_INNER + d;
    const float* bc_p = g_xdbl + ((long)b * SEQ + t0) * 96 + DT_RANK + si;

    float h0 = 0.f, h1 = 0.f, P0 = 1.f, P1 = 1.f;
#pragma unroll 4
    for (int t = 0; t < SLEN; t++) {
        float dt = __ldg(dt_p);
        float xv = __ldg(xc_p);
        float2 Bv = *(const float2*)bc_p;
        float dA0 = __expf(dt * a0);
        float dA1 = __expf(dt * a1);
        float dtx = dt * xv;
        h0 = fmaf(dA0, h0, dtx * Bv.x);
        h1 = fmaf(dA1, h1, dtx * Bv.y);
        P0 *= dA0; P1 *= dA1;
        dt_p += D_INNER; xc_p += D_INNER; bc_p += 96;
    }
    long o = ((long)c * D_STATE + si) * SCHUNK + ck;
    g_P[o] = P0; g_hl[o] = h0;
    g_P[o + SCHUNK] = P1; g_hl[o + SCHUNK] = h1;
}

// ---------------------------------------------------------------------------
// Pass 2: sequential chunk prefix per (c,s): hs[0]=0; hs[i+1]=P[i]*hs[i]+hl[i]
// ---------------------------------------------------------------------------
__global__ void __launch_bounds__(256)
scan_pass2()
{
    int i = blockIdx.x * 256 + threadIdx.x;       // 0..65535
    long base = (long)i * SCHUNK;
    float hs = 0.f;
#pragma unroll
    for (int ck = 0; ck < SCHUNK; ck++) {
        g_hs[base + ck] = hs;
        hs = fmaf(g_P[base + ck], hs, g_hl[base + ck]);
    }
}

// ---------------------------------------------------------------------------
// Pass 3, 2 states/thread: re-run each chunk from correct start state;
// 8-lane (3-shfl) reduce over state pairs; emit y.
// ---------------------------------------------------------------------------
__global__ void __launch_bounds__(128)
scan_pass3(const float* __restrict__ A_log, const float* __restrict__ Dp)
{
    int tid = blockIdx.x * 128 + threadIdx.x;
    int sp = tid & 7;
    int ck = (tid >> 3) & (SCHUNK - 1);
    int c  = tid >> 7;
    int d  = c & (D_INNER - 1);
    int b  = c >> 11;
    int si = sp * 2;

    const float a0 = -__expf(A_log[d * D_STATE + si]);
    const float a1 = -__expf(A_log[d * D_STATE + si + 1]);
    const float Dv = Dp[d];
    long ho = ((long)c * D_STATE + si) * SCHUNK + ck;
    float h0 = g_hs[ho];
    float h1 = g_hs[ho + SCHUNK];

    const int t0 = ck * SLEN;
    const float* dt_p = g_dt   + ((long)b * SEQ + t0) * D_INNER + d;
    const float* xc_p = g_xc   + ((long)b * SEQ + t0) * D_INNER + d;
    const float* z_p  = g_xz   + ((long)b * SEQ + t0) * (2 * D_INNER) + D_INNER + d;
    const float* bc_p = g_xdbl + ((long)b * SEQ + t0) * 96 + DT_RANK + si;
    long yo = ((long)b * SEQ + t0) * D_INNER + d;

#pragma unroll 2
    for (int t = 0; t < SLEN; t++) {
        float dt = __ldg(dt_p);
        float xv = __ldg(xc_p);
        float2 Bv = *(const float2*)bc_p;
        float2 Cv = *(const float2*)(bc_p + D_STATE);

        float dA0 = __expf(dt * a0);
        float dA1 = __expf(dt * a1);
        float dtx = dt * xv;
        h0 = fmaf(dA0, h0, dtx * Bv.x);
        h1 = fmaf(dA1, h1, dtx * Bv.y);

        float p = fmaf(h1, Cv.y, h0 * Cv.x);
        p += __shfl_xor_sync(0xffffffffu, p, 4);
        p += __shfl_xor_sync(0xffffffffu, p, 2);
        p += __shfl_xor_sync(0xffffffffu, p, 1);

        if (sp == 0) {
            float z  = __ldg(z_p);
            float yv = fmaf(Dv, xv, p);
            float sg = __fdividef(1.f, 1.f + __expf(-z));
            g_y[yo] = yv * z * sg;
        }
        dt_p += D_INNER; xc_p += D_INNER; z_p += 2 * D_INNER; bc_p += 96;
        yo += D_INNER;
    }
}

// ---------------------------------------------------------------------------
// Host side
// ---------------------------------------------------------------------------
extern "C" void kernel_launch(void* const* d_in, const int* in_sizes, int n_in,
                              void* d_out, int out_size)
{
    const float* x          = (const float*)d_in[0];
    const float* in_proj_w  = (const float*)d_in[1];
    const float* conv_w     = (const float*)d_in[2];
    const float* conv_b     = (const float*)d_in[3];
    const float* x_proj_w   = (const float*)d_in[4];
    const float* dt_proj_w  = (const float*)d_in[5];
    const float* dt_proj_b  = (const float*)d_in[6];
    const float* A_log      = (const float*)d_in[7];
    const float* Dp         = (const float*)d_in[8];
    const float* out_proj_w = (const float*)d_in[9];
    float* out = (float*)d_out;

    float *xz, *xc, *xdbl, *dt, *y;
    cudaGetSymbolAddress((void**)&xz,   g_xz);
    cudaGetSymbolAddress((void**)&xc,   g_xc);
    cudaGetSymbolAddress((void**)&xdbl, g_xdbl);
    cudaGetSymbolAddress((void**)&dt,   g_dt);
    cudaGetSymbolAddress((void**)&y,    g_y);
    char *xa,*xb,*w1a,*w1b,*oa,*ob,*ya,*yb;
    float *sx,*sw1,*so,*sy;
    cudaGetSymbolAddress((void**)&xa,  q_xa);  cudaGetSymbolAddress((void**)&xb,  q_xb);
    cudaGetSymbolAddress((void**)&w1a, q_w1a); cudaGetSymbolAddress((void**)&w1b, q_w1b);
    cudaGetSymbolAddress((void**)&oa,  q_oa);  cudaGetSymbolAddress((void**)&ob,  q_ob);
    cudaGetSymbolAddress((void**)&ya,  q_ya);  cudaGetSymbolAddress((void**)&yb,  q_yb);
    cudaGetSymbolAddress((void**)&sx,  g_s_x); cudaGetSymbolAddress((void**)&sw1, g_s_w1);
    cudaGetSymbolAddress((void**)&so,  g_s_o); cudaGetSymbolAddress((void**)&sy,  g_s_y);
    bf16 *xch,*xcl,*xwh,*xwl,*dth,*dtl,*dwh,*dwl;
    cudaGetSymbolAddress((void**)&xch, g_xch); cudaGetSymbolAddress((void**)&xcl, g_xcl);
    cudaGetSymbolAddress((void**)&xwh, g_xwh); cudaGetSymbolAddress((void**)&xwl, g_xwl);
    cudaGetSymbolAddress((void**)&dth, g_dth); cudaGetSymbolAddress((void**)&dtl, g_dtl);
    cudaGetSymbolAddress((void**)&dwh, g_dwh); cudaGetSymbolAddress((void**)&dwl, g_dwl);

    // quantize G1 operands (launches 0-2), then G1 at index 3 (ncu capture slot)
    quant_rows<<<M_TOK, 256>>>(x, D_MODEL, xa, xb, sx);
    quant_rows<<<2*D_INNER, 256>>>(in_proj_w, D_MODEL, w1a, w1b, sw1);
    quant_rows<<<D_MODEL, 256>>>(out_proj_w, D_INNER, oa, ob, so);

    // G1: xz = x @ in_proj_w^T  [4096, 4096], K=1024 (int8x3)
    gemm_imma<128,128,32,32,512><<<dim3(32, 32), 512>>>(
        xa, xb, D_MODEL, w1a, w1b, D_MODEL, sx, sw1, xz, 2*D_INNER, D_MODEL);

    // conv + silu (+ bf16 hi/lo for G2)
    {
        long n = (long)M_TOK * D_INNER;
        conv_silu_kernel<<<(int)((n + 255) / 256), 256>>>(conv_w, conv_b);
    }

    // G2: xdbl = xc @ x_proj_w^T  [4096, 96], K=2048 (bf16x3)
    {
        long n = (long)96 * D_INNER;
        cvt_split<<<(int)((n+255)/256),256>>>(x_proj_w, D_INNER, 11, xwh, xwl, n);
    }
    gemm_mma<64,96,16,48,256,0><<<dim3(1, 64), 256>>>(
        xch, xcl, D_INNER, xwh, xwl, D_INNER, xdbl, 96, D_INNER, nullptr);

    // G3: dt = softplus(dt_lo @ dt_proj_w^T + b)  [4096, 2048], K=64 (bf16x3)
    {
        long n = (long)M_TOK * DT_RANK;
        cvt_split<<<(int)((n+255)/256),256>>>(xdbl, 96, 6, dth, dtl, n);
        n = (long)D_INNER * DT_RANK;
        cvt_split<<<(int)((n+255)/256),256>>>(dt_proj_w, DT_RANK, 6, dwh, dwl, n);
    }
    gemm_mma<128,128,32,32,512,1><<<dim3(16, 32), 512>>>(
        dth, dtl, DT_RANK, dwh, dwl, DT_RANK, dt, D_INNER, DT_RANK, dt_proj_b);

    // chunked selective scan, 2 states/thread
    scan_pass1<<<(M_TOK * D_STATE * SCHUNK / 2) / 128, 128>>>(A_log);
    scan_pass2<<<(M_TOK * D_STATE) / 256, 256>>>();
    scan_pass3<<<(M_TOK * D_STATE * SCHUNK / 2) / 128, 128>>>(A_log, Dp);

    // quantize y, then G4: out = y @ out_proj_w^T  [4096, 1024], K=2048 (int8x3)
    quant_rows<<<M_TOK, 256>>>(y, D_INNER, ya, yb, sy);
    gemm_imma<128,128,32,32,512><<<dim3(8, 32), 512>>>(
        ya, yb, D_INNER, oa, ob, D_INNER, sy, so, out, D_MODEL, D_INNER);
}

// round 14
// speedup vs baseline: 2.1056x; 1.0305x over previous
#include <cuda_runtime.h>
#include <cuda_bf16.h>
#include <cuda_pipeline.h>
#include <math.h>
#include <stdint.h>

// ---------------------------------------------------------------------------
// Mamba block forward.
// G1/G2/G4: int8x3 IMMA m16n8k32. G3: bf16x3 mma.sync m16n8k16.
// Scan: chunked linear recurrence (16 x 128), passes 1/3 tiled as
// (b, chunk, 32-channel) blocks with dt/xc/B/C staged in smem (coalesced
// float4 loads; kills the 2048x B/C L2 redundancy).
// Conservative build: static smem <=48KB, __pipeline intrinsics only.
// ---------------------------------------------------------------------------

#define D_MODEL  1024
#define D_STATE  16
#define D_CONV   4
#define D_INNER  2048
#define DT_RANK  64
#define BATCH    2
#define SEQ      2048
#define M_TOK    (BATCH * SEQ)   // 4096
#define SCHUNK   16
#define SLEN     (SEQ / SCHUNK)  // 128

typedef __nv_bfloat16 bf16;

// fp32 scratch
__device__ float g_xz  [(size_t)M_TOK * 2 * D_INNER];
__device__ float g_xc  [(size_t)M_TOK * D_INNER];
__device__ float g_xdbl[(size_t)M_TOK * 96];
__device__ float g_dt  [(size_t)M_TOK * D_INNER];
__device__ float g_y   [(size_t)M_TOK * D_INNER];

// chunked-scan scratch: [(c*16+s)*16+ck]
__device__ float g_P [(size_t)M_TOK * D_STATE * SCHUNK];
__device__ float g_hl[(size_t)M_TOK * D_STATE * SCHUNK];
__device__ float g_hs[(size_t)M_TOK * D_STATE * SCHUNK];

// int8 operands (+ per-row scales)
__device__ char  q_xa [(size_t)M_TOK * D_MODEL],  q_xb [(size_t)M_TOK * D_MODEL];
__device__ char  q_w1a[(size_t)2*D_INNER*D_MODEL],q_w1b[(size_t)2*D_INNER*D_MODEL];
__device__ char  q_oa [(size_t)D_MODEL * D_INNER],q_ob [(size_t)D_MODEL * D_INNER];
__device__ char  q_ya [(size_t)M_TOK * D_INNER],  q_yb [(size_t)M_TOK * D_INNER];
__device__ char  q_xca[(size_t)M_TOK * D_INNER],  q_xcb[(size_t)M_TOK * D_INNER];
__device__ char  q_xwa[(size_t)96 * D_INNER],     q_xwb[(size_t)96 * D_INNER];
__device__ float g_s_x[M_TOK], g_s_w1[2*D_INNER], g_s_o[D_MODEL], g_s_y[M_TOK];
__device__ float g_s_xc[M_TOK], g_s_xw[96];

// bf16 hi/lo operands for G3
__device__ bf16 g_dth[(size_t)M_TOK * DT_RANK],  g_dtl[(size_t)M_TOK * DT_RANK];
__device__ bf16 g_dwh[(size_t)D_INNER * DT_RANK],g_dwl[(size_t)D_INNER * DT_RANK];

// ---------------------------------------------------------------------------
__device__ __forceinline__ uint32_t smem_u32(const void* p) {
    uint32_t a;
    asm("{ .reg .u64 t; cvta.to.shared.u64 t, %1; cvt.u32.u64 %0, t; }"
        : "=r"(a) : "l"(p));
    return a;
}

#define LDSM4(r0, r1, r2, r3, addr) \
    asm volatile("ldmatrix.sync.aligned.m8n8.x4.shared.b16 {%0,%1,%2,%3}, [%4];" \
        : "=r"(r0), "=r"(r1), "=r"(r2), "=r"(r3) : "r"(addr))

#define MMA_BF16(d, a, b) \
    asm volatile("mma.sync.aligned.m16n8k16.row.col.f32.bf16.bf16.f32 " \
        "{%0,%1,%2,%3}, {%4,%5,%6,%7}, {%8,%9}, {%0,%1,%2,%3};" \
        : "+f"((d)[0]), "+f"((d)[1]), "+f"((d)[2]), "+f"((d)[3]) \
        : "r"((a)[0]), "r"((a)[1]), "r"((a)[2]), "r"((a)[3]), \
          "r"((b)[0]), "r"((b)[1]))

#define MMA_S8(d, a, b) \
    asm volatile("mma.sync.aligned.m16n8k32.row.col.s32.s8.s8.s32 " \
        "{%0,%1,%2,%3}, {%4,%5,%6,%7}, {%8,%9}, {%0,%1,%2,%3};" \
        : "+r"((d)[0]), "+r"((d)[1]), "+r"((d)[2]), "+r"((d)[3]) \
        : "r"((a)[0]), "r"((a)[1]), "r"((a)[2]), "r"((a)[3]), \
          "r"((b)[0]), "r"((b)[1]))

// ---------------------------------------------------------------------------
// int8 GEMM:  C[m,n] = sA[m]*sB[n]*(Q1a.Q1b + (Q2a.Q1b + Q1a.Q2b)/128)
// ---------------------------------------------------------------------------
template<int BM, int BN, int WM, int WN, int THREADS>
__device__ __forceinline__ void stage_load_i8(
    char* sb, const char* a1, const char* a2, int lda,
    const char* b1, const char* b2, int ldb, int koff, int tid)
{
    constexpr int RT = 2 * BM + 2 * BN;
#pragma unroll
    for (int e = tid; e < RT * 2; e += THREADS) {
        const int r = e >> 1, c = e & 1;
        char* dst = sb + (r << 5) + ((c ^ ((r >> 2) & 1)) << 4);
        const char* src;
        if (r < BM)               src = a1 + (long)r * lda + koff + c * 16;
        else if (r < 2 * BM)      src = a2 + (long)(r - BM) * lda + koff + c * 16;
        else if (r < 2 * BM + BN) src = b1 + (long)(r - 2 * BM) * ldb + koff + c * 16;
        else                      src = b2 + (long)(r - 2 * BM - BN) * ldb + koff + c * 16;
        __pipeline_memcpy_async(dst, src, 16);
    }
    __pipeline_commit();
}

template<int BM, int BN, int WM, int WN, int THREADS>
__global__ void __launch_bounds__(THREADS)
gemm_imma(const char* __restrict__ A1, const char* __restrict__ A2, int lda,
          const char* __restrict__ B1, const char* __restrict__ B2, int ldb,
          const float* __restrict__ sA, const float* __restrict__ sB,
          float* __restrict__ C, int ldc, int K)
{
    constexpr int STAGE_B = (2 * BM + 2 * BN) * 32;
    constexpr int WARPS_N = BN / WN;
    constexpr int MA = WM / 16;
    constexpr int NA = WN / 8;

    __shared__ __align__(128) char smem[3 * STAGE_B];

    const int tid = threadIdx.x, wid = tid >> 5, lane = tid & 31;
    const int wm = wid / WARPS_N, wn = wid % WARPS_N;
    const int m0 = blockIdx.y * BM;
    const int n0 = blockIdx.x * BN;
    const int KT = K >> 5;

    const char* a1 = A1 + (long)m0 * lda;
    const char* a2 = A2 + (long)m0 * lda;
    const char* b1 = B1 + (long)n0 * ldb;
    const char* b2 = B2 + (long)n0 * ldb;

    int acc1[MA][NA][4], acc2[MA][NA][4];
#pragma unroll
    for (int i = 0; i < MA; i++)
#pragma unroll
        for (int j = 0; j < NA; j++)
#pragma unroll
            for (int e = 0; e < 4; e++) { acc1[i][j][e] = 0; acc2[i][j][e] = 0; }

    const int a_row  = wm * WM + (lane & 15);
    const int a_csel = lane >> 4;
    const int bg     = lane >> 3;
    const int b_row  = wn * WN + (lane & 7) + ((bg >> 1) << 3);
    const int b_csel = bg & 1;

    const uint32_t s0 = smem_u32(smem);

    stage_load_i8<BM,BN,WM,WN,THREADS>(smem, a1, a2, lda, b1, b2, ldb, 0, tid);
    if (KT > 1)
        stage_load_i8<BM,BN,WM,WN,THREADS>(smem + STAGE_B, a1, a2, lda, b1, b2, ldb, 32, tid);
    else
        __pipeline_commit();

    int cs = 0;
    for (int kt = 0; kt < KT; ++kt) {
        __pipeline_wait_prior(1);
        __syncthreads();

        const uint32_t base = s0 + cs * STAGE_B;
        const uint32_t pA1 = base;
        const uint32_t pA2 = base + BM * 32;
        const uint32_t pB1 = base + 2 * BM * 32;
        const uint32_t pB2 = pB1 + BN * 32;

        uint32_t ar1[MA][4], ar2[MA][4], br1[NA][2], br2[NA][2];
#pragma unroll
        for (int ma = 0; ma < MA; ++ma) {
            const int r = a_row + ma * 16;
            const uint32_t off = r * 32 + ((a_csel ^ ((r >> 2) & 1)) << 4);
            LDSM4(ar1[ma][0], ar1[ma][1], ar1[ma][2], ar1[ma][3], pA1 + off);
            LDSM4(ar2[ma][0], ar2[ma][1], ar2[ma][2], ar2[ma][3], pA2 + off);
        }
#pragma unroll
        for (int p = 0; p < NA / 2; ++p) {
            const int r = b_row + p * 16;
            const uint32_t off = r * 32 + ((b_csel ^ ((r >> 2) & 1)) << 4);
            LDSM4(br1[2*p][0], br1[2*p][1], br1[2*p+1][0], br1[2*p+1][1], pB1 + off);
            LDSM4(br2[2*p][0], br2[2*p][1], br2[2*p+1][0], br2[2*p+1][1], pB2 + off);
        }
#pragma unroll
        for (int ma = 0; ma < MA; ++ma)
#pragma unroll
            for (int na = 0; na < NA; ++na) {
                MMA_S8(acc1[ma][na], ar1[ma], br1[na]);
                MMA_S8(acc2[ma][na], ar2[ma], br1[na]);
                MMA_S8(acc2[ma][na], ar1[ma], br2[na]);
            }

        if (kt + 2 < KT) {
            int ls = cs + 2; if (ls >= 3) ls -= 3;
            stage_load_i8<BM,BN,WM,WN,THREADS>(smem + ls * STAGE_B,
                a1, a2, lda, b1, b2, ldb, (kt + 2) * 32, tid);
        } else {
            __pipeline_commit();
        }
        if (++cs == 3) cs = 0;
    }

    const int er = lane >> 2, ec = (lane & 3) * 2;
#pragma unroll
    for (int ma = 0; ma < MA; ++ma) {
        const int m = m0 + wm * WM + ma * 16 + er;
        const float sa0 = sA[m], sa1 = sA[m + 8];
#pragma unroll
        for (int na = 0; na < NA; ++na) {
            const int n = n0 + wn * WN + na * 8 + ec;
            const float sb0 = sB[n], sb1 = sB[n + 1];
            float2 v0, v1;
            v0.x = sa0 * sb0 * ((float)acc1[ma][na][0] + (float)acc2[ma][na][0] * 0.0078125f);
            v0.y = sa0 * sb1 * ((float)acc1[ma][na][1] + (float)acc2[ma][na][1] * 0.0078125f);
            v1.x = sa1 * sb0 * ((float)acc1[ma][na][2] + (float)acc2[ma][na][2] * 0.0078125f);
            v1.y = sa1 * sb1 * ((float)acc1[ma][na][3] + (float)acc2[ma][na][3] * 0.0078125f);
            *(float2*)(C + (long)m * ldc + n)       = v0;
            *(float2*)(C + (long)(m + 8) * ldc + n) = v1;
        }
    }
}

// ---------------------------------------------------------------------------
// bf16x3 GEMM (G3 only)
// ---------------------------------------------------------------------------
template<int BM, int BN, int THREADS>
__device__ __forceinline__ void stage_load(
    bf16* sb, const bf16* aH, const bf16* aL, int lda,
    const bf16* bH, const bf16* bL, int ldb, int koff, int tid)
{
    constexpr int RT  = 2 * BM + 2 * BN;
#pragma unroll
    for (int e = tid; e < RT * 2; e += THREADS) {
        const int r = e >> 1, c = e & 1;
        bf16* dst = sb + (r << 4) + ((c ^ ((r >> 2) & 1)) << 3);
        const bf16* src;
        if (r < BM)               src = aH + (long)r * lda + koff + c * 8;
        else if (r < 2 * BM)      src = aL + (long)(r - BM) * lda + koff + c * 8;
        else if (r < 2 * BM + BN) src = bH + (long)(r - 2 * BM) * ldb + koff + c * 8;
        else                      src = bL + (long)(r - 2 * BM - BN) * ldb + koff + c * 8;
        __pipeline_memcpy_async(dst, src, 16);
    }
    __pipeline_commit();
}

template<int BM, int BN, int WM, int WN, int THREADS, int EPI>
__global__ void __launch_bounds__(THREADS)
gemm_mma(const bf16* __restrict__ Ah, const bf16* __restrict__ Al, int lda,
         const bf16* __restrict__ Bh, const bf16* __restrict__ Bl, int ldb,
         float* __restrict__ C, int ldc, int K,
         const float* __restrict__ bias)
{
    constexpr int STAGE_E = (2 * BM + 2 * BN) * 16;
    constexpr int WARPS_N = BN / WN;
    constexpr int MA = WM / 16;
    constexpr int NA = WN / 8;

    __shared__ bf16 smem[3 * STAGE_E];

    const int tid = threadIdx.x, wid = tid >> 5, lane = tid & 31;
    const int wm = wid / WARPS_N, wn = wid % WARPS_N;
    const int m0 = blockIdx.y * BM;
    const int n0 = blockIdx.x * BN;
    const int KT = K >> 4;

    const bf16* aH = Ah + (long)m0 * lda;
    const bf16* aL = Al + (long)m0 * lda;
    const bf16* bH = Bh + (long)n0 * ldb;
    const bf16* bL = Bl + (long)n0 * ldb;

    float acc[MA][NA][4];
#pragma unroll
    for (int i = 0; i < MA; i++)
#pragma unroll
        for (int j = 0; j < NA; j++)
#pragma unroll
            for (int e = 0; e < 4; e++) acc[i][j][e] = 0.f;

    const int a_row  = wm * WM + (lane & 15);
    const int a_csel = lane >> 4;
    const int bg     = lane >> 3;
    const int b_row  = wn * WN + (lane & 7) + ((bg >> 1) << 3);
    const int b_csel = bg & 1;

    const uint32_t s0 = smem_u32(smem);

    stage_load<BM, BN, THREADS>(smem, aH, aL, lda, bH, bL, ldb, 0, tid);
    if (KT > 1)
        stage_load<BM, BN, THREADS>(smem + STAGE_E, aH, aL, lda, bH, bL, ldb, 16, tid);
    else
        __pipeline_commit();

    int cs = 0;
    for (int kt = 0; kt < KT; ++kt) {
        __pipeline_wait_prior(1);
        __syncthreads();

        const uint32_t base = s0 + cs * (STAGE_E * 2);
        const uint32_t pAh = base;
        const uint32_t pAl = base + BM * 32;
        const uint32_t pBh = base + 2 * BM * 32;
        const uint32_t pBl = pBh + BN * 32;

        uint32_t ar[MA][4], alr[MA][4], br[NA][2], blr[NA][2];
#pragma unroll
        for (int ma = 0; ma < MA; ++ma) {
            const int r = a_row + ma * 16;
            const uint32_t off = r * 32 + ((a_csel ^ ((r >> 2) & 1)) << 4);
            LDSM4(ar[ma][0],  ar[ma][1],  ar[ma][2],  ar[ma][3],  pAh + off);
            LDSM4(alr[ma][0], alr[ma][1], alr[ma][2], alr[ma][3], pAl + off);
        }
#pragma unroll
        for (int p = 0; p < NA / 2; ++p) {
            const int r = b_row + p * 16;
            const uint32_t off = r * 32 + ((b_csel ^ ((r >> 2) & 1)) << 4);
            LDSM4(br[2*p][0],  br[2*p][1],  br[2*p+1][0],  br[2*p+1][1],  pBh + off);
            LDSM4(blr[2*p][0], blr[2*p][1], blr[2*p+1][0], blr[2*p+1][1], pBl + off);
        }
#pragma unroll
        for (int ma = 0; ma < MA; ++ma)
#pragma unroll
            for (int na = 0; na < NA; ++na) {
                MMA_BF16(acc[ma][na], ar[ma],  br[na]);
                MMA_BF16(acc[ma][na], alr[ma], br[na]);
                MMA_BF16(acc[ma][na], ar[ma],  blr[na]);
            }

        if (kt + 2 < KT) {
            int ls = cs + 2; if (ls >= 3) ls -= 3;
            stage_load<BM, BN, THREADS>(smem + ls * STAGE_E,
                                        aH, aL, lda, bH, bL, ldb, (kt + 2) * 16, tid);
        } else {
            __pipeline_commit();
        }
        if (++cs == 3) cs = 0;
    }

    const int er = lane >> 2, ec = (lane & 3) * 2;
#pragma unroll
    for (int ma = 0; ma < MA; ++ma) {
#pragma unroll
        for (int na = 0; na < NA; ++na) {
            const int m = m0 + wm * WM + ma * 16 + er;
            const int n = n0 + wn * WN + na * 8 + ec;
            float2 v0 = {acc[ma][na][0], acc[ma][na][1]};
            float2 v1 = {acc[ma][na][2], acc[ma][na][3]};
            if (EPI == 1) {
                const float b0 = bias[n], b1 = bias[n + 1];
                v0.x += b0; v0.y += b1; v1.x += b0; v1.y += b1;
                v0.x = (v0.x > 20.f) ? v0.x : log1pf(__expf(v0.x));
                v0.y = (v0.y > 20.f) ? v0.y : log1pf(__expf(v0.y));
                v1.x = (v1.x > 20.f) ? v1.x : log1pf(__expf(v1.x));
                v1.y = (v1.y > 20.f) ? v1.y : log1pf(__expf(v1.y));
            }
            *(float2*)(C + (long)m * ldc + n)       = v0;
            *(float2*)(C + (long)(m + 8) * ldc + n) = v1;
        }
    }
}

// ---------------------------------------------------------------------------
// Per-row int8x2 quantization
// ---------------------------------------------------------------------------
__global__ void __launch_bounds__(256)
quant_rows(const float* __restrict__ src, int cols,
           char* __restrict__ q1, char* __restrict__ q2,
           float* __restrict__ scale)
{
    __shared__ float red[8];
    const int row = blockIdx.x, tid = threadIdx.x;
    const float* rp = src + (long)row * cols;
    const int nv = cols >> 10;
    float4 v[2];
    float m = 0.f;
    for (int i = 0; i < nv; i++) {
        v[i] = *(const float4*)(rp + tid * 4 + i * 1024);
        m = fmaxf(m, fmaxf(fmaxf(fabsf(v[i].x), fabsf(v[i].y)),
                           fmaxf(fabsf(v[i].z), fabsf(v[i].w))));
    }
    for (int o = 16; o; o >>= 1) m = fmaxf(m, __shfl_xor_sync(0xffffffffu, m, o));
    if ((tid & 31) == 0) red[tid >> 5] = m;
    __syncthreads();
    if (tid < 32) {
        float t = (tid < 8) ? red[tid] : 0.f;
        for (int o = 4; o; o >>= 1) t = fmaxf(t, __shfl_xor_sync(0xffffffffu, t, o));
        if (tid == 0) red[0] = t;
    }
    __syncthreads();
    const float bm  = red[0];
    const float s   = (bm > 1e-30f) ? bm * (1.f / 127.f) : 1.f;
    const float rcp = (bm > 1e-30f) ? 127.f / bm : 0.f;
    for (int i = 0; i < nv; i++) {
        const long o = (long)row * cols + tid * 4 + i * 1024;
        float f[4] = {v[i].x, v[i].y, v[i].z, v[i].w};
        char c1[4], c2[4];
#pragma unroll
        for (int j = 0; j < 4; j++) {
            float t = f[j] * rcp;
            int a = __float2int_rn(t);
            int b = __float2int_rn((t - (float)a) * 128.f);
            c1[j] = (char)a; c2[j] = (char)b;
        }
        *(char4*)(q1 + o) = make_char4(c1[0], c1[1], c1[2], c1[3]);
        *(char4*)(q2 + o) = make_char4(c2[0], c2[1], c2[2], c2[3]);
    }
    if (tid == 0) scale[row] = s;
}

// ---------------------------------------------------------------------------
__global__ void cvt_split(const float* __restrict__ src, int ld, int lc,
                          bf16* __restrict__ hi, bf16* __restrict__ lo, long total)
{
    long i = (long)blockIdx.x * blockDim.x + threadIdx.x;
    if (i >= total) return;
    long r = i >> lc;
    int c = (int)(i & ((1 << lc) - 1));
    float v = src[r * ld + c];
    bf16 h = __float2bfloat16(v);
    hi[i] = h;
    lo[i] = __float2bfloat16(v - __bfloat162float(h));
}

// ---------------------------------------------------------------------------
// Depthwise causal conv (4-tap) + SiLU -> g_xc (fp32 only; quantized after)
// ---------------------------------------------------------------------------
__global__ void conv_silu_kernel(const float* __restrict__ conv_w,
                                 const float* __restrict__ conv_b)
{
    long idx = (long)blockIdx.x * blockDim.x + threadIdx.x;
    if (idx >= (long)M_TOK * D_INNER) return;
    int d = (int)(idx & (D_INNER - 1));
    long m = idx >> 11;
    int t = (int)(m & (SEQ - 1));
    long row0 = m - t;

    float acc = conv_b[d];
    const float* w = conv_w + d * 4;
#pragma unroll
    for (int j = 0; j < D_CONV; j++) {
        int tt = t - (D_CONV - 1) + j;
        if (tt >= 0)
            acc = fmaf(g_xz[(row0 + tt) * (2 * D_INNER) + d], w[j], acc);
    }
    float s = __fdividef(1.f, 1.f + __expf(-acc));
    g_xc[m * D_INNER + d] = acc * s;
}

// ---------------------------------------------------------------------------
// Chunked scan pass 1, smem-tiled: block = (b, ck, 32-channel tile), 256 thr
// (ci = tid>>3, sp = tid&7). Stages dt/xc/B slices; computes P, h_l.
// ---------------------------------------------------------------------------
__global__ void __launch_bounds__(256)
scan_pass1(const float* __restrict__ A_log)
{
    __shared__ float s_dt[SLEN][32];
    __shared__ float s_xc[SLEN][32];
    __shared__ float s_b [SLEN][16];

    const int bx = blockIdx.x;
    const int ck = bx & (SCHUNK - 1);
    const int tile = (bx >> 4) & 63;
    const int b = bx >> 10;
    const int d0 = tile * 32;
    const int tid = threadIdx.x;
    const int sp = tid & 7, ci = tid >> 3;
    const int d = d0 + ci, si = sp * 2;
    const int t0 = ck * SLEN;

    for (int e = tid; e < SLEN * 8; e += 256) {
        const int t = e >> 3, j = (e & 7) * 4;
        const long row = (long)(b * SEQ + t0 + t);
        *(float4*)&s_dt[t][j] = *(const float4*)(g_dt + row * D_INNER + d0 + j);
        *(float4*)&s_xc[t][j] = *(const float4*)(g_xc + row * D_INNER + d0 + j);
    }
    for (int e = tid; e < SLEN * 4; e += 256) {
        const int t = e >> 2, j = (e & 3) * 4;
        const long row = (long)(b * SEQ + t0 + t);
        *(float4*)&s_b[t][j] = *(const float4*)(g_xdbl + row * 96 + DT_RANK + j);
    }
    __syncthreads();

    const float a0 = -__expf(A_log[d * D_STATE + si]);
    const float a1 = -__expf(A_log[d * D_STATE + si + 1]);

    float h0 = 0.f, h1 = 0.f, P0 = 1.f, P1 = 1.f;
#pragma unroll 4
    for (int t = 0; t < SLEN; t++) {
        float dt = s_dt[t][ci];
        float xv = s_xc[t][ci];
        float2 Bv = *(const float2*)&s_b[t][si];
        float dA0 = __expf(dt * a0);
        float dA1 = __expf(dt * a1);
        float dtx = dt * xv;
        h0 = fmaf(dA0, h0, dtx * Bv.x);
        h1 = fmaf(dA1, h1, dtx * Bv.y);
        P0 *= dA0; P1 *= dA1;
    }
    const int c = b * D_INNER + d;
    long o = ((long)c * D_STATE + si) * SCHUNK + ck;
    g_P[o] = P0; g_hl[o] = h0;
    g_P[o + SCHUNK] = P1; g_hl[o + SCHUNK] = h1;
}

// ---------------------------------------------------------------------------
// Pass 2: sequential chunk prefix per (c,s)
// ---------------------------------------------------------------------------
__global__ void __launch_bounds__(256)
scan_pass2()
{
    int i = blockIdx.x * 256 + threadIdx.x;
    long base = (long)i * SCHUNK;
    float hs = 0.f;
#pragma unroll
    for (int ck = 0; ck < SCHUNK; ck++) {
        g_hs[base + ck] = hs;
        hs = fmaf(g_P[base + ck], hs, g_hl[base + ck]);
    }
}

// ---------------------------------------------------------------------------
// Pass 3, smem-tiled: stages dt/xc/B+C; re-runs chunk from start state,
// 8-lane (3-shfl) reduce, emits y. smem = 48KB.
// ---------------------------------------------------------------------------
__global__ void __launch_bounds__(256)
scan_pass3(const float* __restrict__ A_log, const float* __restrict__ Dp)
{
    __shared__ float s_dt[SLEN][32];
    __shared__ float s_xc[SLEN][32];
    __shared__ float s_bc[SLEN][32];   // [0:16)=B, [16:32)=C

    const int bx = blockIdx.x;
    const int ck = bx & (SCHUNK - 1);
    const int tile = (bx >> 4) & 63;
    const int b = bx >> 10;
    const int d0 = tile * 32;
    const int tid = threadIdx.x;
    const int sp = tid & 7, ci = tid >> 3;
    const int d = d0 + ci, si = sp * 2;
    const int t0 = ck * SLEN;

    for (int e = tid; e < SLEN * 8; e += 256) {
        const int t = e >> 3, j = (e & 7) * 4;
        const long row = (long)(b * SEQ + t0 + t);
        *(float4*)&s_dt[t][j] = *(const float4*)(g_dt + row * D_INNER + d0 + j);
        *(float4*)&s_xc[t][j] = *(const float4*)(g_xc + row * D_INNER + d0 + j);
        *(float4*)&s_bc[t][j] = *(const float4*)(g_xdbl + row * 96 + DT_RANK + j);
    }
    __syncthreads();

    const float a0 = -__expf(A_log[d * D_STATE + si]);
    const float a1 = -__expf(A_log[d * D_STATE + si + 1]);
    const float Dv = Dp[d];
    const int c = b * D_INNER + d;
    long ho = ((long)c * D_STATE + si) * SCHUNK + ck;
    float h0 = g_hs[ho];
    float h1 = g_hs[ho + SCHUNK];

    const float* z_p = g_xz + (long)(b * SEQ + t0) * (2 * D_INNER) + D_INNER + d;
    long yo = (long)(b * SEQ + t0) * D_INNER + d;

#pragma unroll 2
    for (int t = 0; t < SLEN; t++) {
        float dt = s_dt[t][ci];
        float xv = s_xc[t][ci];
        float2 Bv = *(const float2*)&s_bc[t][si];
        float2 Cv = *(const float2*)&s_bc[t][16 + si];

        float dA0 = __expf(dt * a0);
        float dA1 = __expf(dt * a1);
        float dtx = dt * xv;
        h0 = fmaf(dA0, h0, dtx * Bv.x);
        h1 = fmaf(dA1, h1, dtx * Bv.y);

        float p = fmaf(h1, Cv.y, h0 * Cv.x);
        p += __shfl_xor_sync(0xffffffffu, p, 4);
        p += __shfl_xor_sync(0xffffffffu, p, 2);
        p += __shfl_xor_sync(0xffffffffu, p, 1);

        if (sp == 0) {
            float z  = __ldg(z_p);
            float yv = fmaf(Dv, xv, p);
            float sg = __fdividef(1.f, 1.f + __expf(-z));
            g_y[yo] = yv * z * sg;
        }
        z_p += 2 * D_INNER; yo += D_INNER;
    }
}

// ---------------------------------------------------------------------------
// Host side
// ---------------------------------------------------------------------------
extern "C" void kernel_launch(void* const* d_in, const int* in_sizes, int n_in,
                              void* d_out, int out_size)
{
    const float* x          = (const float*)d_in[0];
    const float* in_proj_w  = (const float*)d_in[1];
    const float* conv_w     = (const float*)d_in[2];
    const float* conv_b     = (const float*)d_in[3];
    const float* x_proj_w   = (const float*)d_in[4];
    const float* dt_proj_w  = (const float*)d_in[5];
    const float* dt_proj_b  = (const float*)d_in[6];
    const float* A_log      = (const float*)d_in[7];
    const float* Dp         = (const float*)d_in[8];
    const float* out_proj_w = (const float*)d_in[9];
    float* out = (float*)d_out;

    float *xz, *xc, *xdbl, *dt, *y;
    cudaGetSymbolAddress((void**)&xz,   g_xz);
    cudaGetSymbolAddress((void**)&xc,   g_xc);
    cudaGetSymbolAddress((void**)&xdbl, g_xdbl);
    cudaGetSymbolAddress((void**)&dt,   g_dt);
    cudaGetSymbolAddress((void**)&y,    g_y);
    char *xa,*xb,*w1a,*w1b,*oa,*ob,*ya,*yb,*xca,*xcb,*xwa,*xwb;
    float *sx,*sw1,*so,*sy,*sxc,*sxw;
    cudaGetSymbolAddress((void**)&xa,  q_xa);  cudaGetSymbolAddress((void**)&xb,  q_xb);
    cudaGetSymbolAddress((void**)&w1a, q_w1a); cudaGetSymbolAddress((void**)&w1b, q_w1b);
    cudaGetSymbolAddress((void**)&oa,  q_oa);  cudaGetSymbolAddress((void**)&ob,  q_ob);
    cudaGetSymbolAddress((void**)&ya,  q_ya);  cudaGetSymbolAddress((void**)&yb,  q_yb);
    cudaGetSymbolAddress((void**)&xca, q_xca); cudaGetSymbolAddress((void**)&xcb, q_xcb);
    cudaGetSymbolAddress((void**)&xwa, q_xwa); cudaGetSymbolAddress((void**)&xwb, q_xwb);
    cudaGetSymbolAddress((void**)&sx,  g_s_x); cudaGetSymbolAddress((void**)&sw1, g_s_w1);
    cudaGetSymbolAddress((void**)&so,  g_s_o); cudaGetSymbolAddress((void**)&sy,  g_s_y);
    cudaGetSymbolAddress((void**)&sxc, g_s_xc);cudaGetSymbolAddress((void**)&sxw, g_s_xw);
    bf16 *dth,*dtl,*dwh,*dwl;
    cudaGetSymbolAddress((void**)&dth, g_dth); cudaGetSymbolAddress((void**)&dtl, g_dtl);
    cudaGetSymbolAddress((void**)&dwh, g_dwh); cudaGetSymbolAddress((void**)&dwl, g_dwl);

    // quantize G1 operands (launches 0-2), then G1 at index 3 (ncu capture slot)
    quant_rows<<<M_TOK, 256>>>(x, D_MODEL, xa, xb, sx);
    quant_rows<<<2*D_INNER, 256>>>(in_proj_w, D_MODEL, w1a, w1b, sw1);
    quant_rows<<<D_MODEL, 256>>>(out_proj_w, D_INNER, oa, ob, so);

    // G1: xz = x @ in_proj_w^T  [4096, 4096], K=1024 (int8x3)
    gemm_imma<128,128,32,32,512><<<dim3(32, 32), 512>>>(
        xa, xb, D_MODEL, w1a, w1b, D_MODEL, sx, sw1, xz, 2*D_INNER, D_MODEL);

    // conv + silu
    {
        long n = (long)M_TOK * D_INNER;
        conv_silu_kernel<<<(int)((n + 255) / 256), 256>>>(conv_w, conv_b);
    }

    // G2: xdbl = xc @ x_proj_w^T  [4096, 96], K=2048 (int8x3, BM=32 -> 128 CTAs)
    quant_rows<<<M_TOK, 256>>>(xc, D_INNER, xca, xcb, sxc);
    quant_rows<<<96, 256>>>(x_proj_w, D_INNER, xwa, xwb, sxw);
    gemm_imma<32,96,16,48,128><<<dim3(1, 128), 128>>>(
        xca, xcb, D_INNER, xwa, xwb, D_INNER, sxc, sxw, xdbl, 96, D_INNER);

    // G3: dt = softplus(dt_lo @ dt_proj_w^T + b)  [4096, 2048], K=64 (bf16x3)
    {
        long n = (long)M_TOK * DT_RANK;
        cvt_split<<<(int)((n+255)/256),256>>>(xdbl, 96, 6, dth, dtl, n);
        n = (long)D_INNER * DT_RANK;
        cvt_split<<<(int)((n+255)/256),256>>>(dt_proj_w, DT_RANK, 6, dwh, dwl, n);
    }
    gemm_mma<128,128,32,32,512,1><<<dim3(16, 32), 512>>>(
        dth, dtl, DT_RANK, dwh, dwl, DT_RANK, dt, D_INNER, DT_RANK, dt_proj_b);

    // chunked selective scan, smem-tiled passes
    scan_pass1<<<BATCH * SCHUNK * (D_INNER / 32), 256>>>(A_log);
    scan_pass2<<<(M_TOK * D_STATE) / 256, 256>>>();
    scan_pass3<<<BATCH * SCHUNK * (D_INNER / 32), 256>>>(A_log, Dp);

    // quantize y, then G4: out = y @ out_proj_w^T  [4096, 1024], K=2048 (int8x3)
    quant_rows<<<M_TOK, 256>>>(y, D_INNER, ya, yb, sy);
    gemm_imma<128,128,32,32,512><<<dim3(8, 32), 512>>>(
        ya, yb, D_INNER, oa, ob, D_INNER, sy, so, out, D_MODEL, D_INNER);
}